// round 14
// baseline (speedup 1.0000x reference)
#include <cuda_runtime.h>
#include <cuda_fp16.h>
#include <math.h>
#include <stdint.h>

#define NPTS 1024
#define KNB 20
#define BATCH 8
#define CEPS 1e-5f
#define CSLOPE 0.2f

// ---------------- scratch (no allocations allowed) ----------------
__device__ uint32_t g_catH[(size_t)BATCH * 256 * NPTS];
__device__ uint32_t g_catL[(size_t)BATCH * 256 * NPTS];
__device__ float    g_gram[(size_t)BATCH * NPTS * NPTS];
__device__ float    g_E[(size_t)BATCH * 1024 * NPTS];
__device__ float    g_xx[BATCH * NPTS];
__device__ int      g_idx[(size_t)BATCH * NPTS * KNB];
__device__ float    g_Z[(size_t)BATCH * NPTS * 512];
__device__ uint32_t g_WtH[45312], g_WtL[45312];
__device__ uint32_t g_weTH[256 * 1024], g_weTL[256 * 1024];
__device__ uint32_t g_xH[BATCH * 2 * NPTS], g_xL[BATCH * 2 * NPTS];
__device__ float    g_pmax[BATCH * NPTS * 8];
__device__ float    g_psum[BATCH * NPTS * 8];

#define WSEG0 0
#define WSEG1 256
#define WSEG2 4352
#define WSEG3 12544
#define WTOTU 45312

// ================= helpers =================
__device__ __forceinline__ uint32_t packh(float a, float b) {
    __half2 h = __halves2half2(__float2half_rn(a), __float2half_rn(b));
    return *(uint32_t*)&h;
}
__device__ __forceinline__ uint32_t packl(float a, float b) {
    float ra = a - __half2float(__float2half_rn(a));
    float rb = b - __half2float(__float2half_rn(b));
    __half2 h = __halves2half2(__float2half_rn(ra), __float2half_rn(rb));
    return *(uint32_t*)&h;
}
__device__ __forceinline__ void mma16(float* c, const uint32_t* a, const uint32_t* b) {
    asm volatile(
        "mma.sync.aligned.m16n8k16.row.col.f32.f16.f16.f32 "
        "{%0,%1,%2,%3}, {%4,%5,%6,%7}, {%8,%9}, {%0,%1,%2,%3};\n"
        : "+f"(c[0]), "+f"(c[1]), "+f"(c[2]), "+f"(c[3])
        : "r"(a[0]), "r"(a[1]), "r"(a[2]), "r"(a[3]), "r"(b[0]), "r"(b[1]));
}
__device__ __forceinline__ void cpa16(uint32_t s, const void* g, int ok) {
    asm volatile("cp.async.cg.shared.global [%0], [%1], 16, %2;"
                 :: "r"(s), "l"(g), "r"(ok ? 16 : 0));
}
__device__ __forceinline__ void cpa_commit() { asm volatile("cp.async.commit_group;"); }
template<int N> __device__ __forceinline__ void cpa_wait() {
    asm volatile("cp.async.wait_group %0;" :: "n"(N));
}

// ================= shared GEMM core, KC=8 pair-rows/stage, 2 CTA/SM =================
// smem per buffer: 4 arrays x 8x136 u32 = 4352 words; double buffered = 34816 B.
struct GemmPtrs {
    const uint32_t *Ah, *Al, *Bh, *Bl;
    int lda, ldb, KP;
};

__device__ __forceinline__ void gemm_mainloop(
    const GemmPtrs& P, uint32_t* smbuf, int tid, int wm, int wn, int qr, int qc,
    float acc[4][4][4])
{
    const int r0 = tid >> 5, c0 = (tid & 31) * 4;
    const uint32_t smbase = (uint32_t)__cvta_generic_to_shared(smbuf);
    const int KT = (P.KP + 7) / 8;

    auto issue = [&](int kt, int buf) {
        const int rl = P.KP - kt * 8;
        const size_t ko = (size_t)kt * 8;
        uint32_t d0 = smbase + (uint32_t)buf * (4352u * 4u) + (uint32_t)(r0 * 136 + c0) * 4u;
        int ok = r0 < rl;
        cpa16(d0,             P.Ah + (ko + r0) * P.lda + c0, ok);
        cpa16(d0 + 1088u * 4, P.Al + (ko + r0) * P.lda + c0, ok);
        cpa16(d0 + 2176u * 4, P.Bh + (ko + r0) * P.ldb + c0, ok);
        cpa16(d0 + 3264u * 4, P.Bl + (ko + r0) * P.ldb + c0, ok);
        cpa_commit();
    };

    issue(0, 0);
    for (int kt = 0; kt < KT; kt++) {
        const int cur = kt & 1;
        if (kt + 1 < KT) { issue(kt + 1, cur ^ 1); cpa_wait<1>(); }
        else             { cpa_wait<0>(); }
        __syncthreads();
        const uint32_t* Ah = smbuf + cur * 4352;
        const uint32_t* Al = Ah + 1088;
        const uint32_t* Bh = Ah + 2176;
        const uint32_t* Bl = Ah + 3264;
        uint32_t ah[4][4], al[4][4], bh[4][2], bl[4][2];
        #pragma unroll
        for (int mt = 0; mt < 4; mt++) {
            int R = wm * 64 + mt * 16;
            ah[mt][0] = Ah[qc * 136 + R + qr];
            ah[mt][1] = Ah[qc * 136 + R + qr + 8];
            ah[mt][2] = Ah[(qc + 4) * 136 + R + qr];
            ah[mt][3] = Ah[(qc + 4) * 136 + R + qr + 8];
            al[mt][0] = Al[qc * 136 + R + qr];
            al[mt][1] = Al[qc * 136 + R + qr + 8];
            al[mt][2] = Al[(qc + 4) * 136 + R + qr];
            al[mt][3] = Al[(qc + 4) * 136 + R + qr + 8];
        }
        #pragma unroll
        for (int nt = 0; nt < 4; nt++) {
            int C0 = wn * 32 + nt * 8;
            bh[nt][0] = Bh[qc * 136 + C0 + qr];
            bh[nt][1] = Bh[(qc + 4) * 136 + C0 + qr];
            bl[nt][0] = Bl[qc * 136 + C0 + qr];
            bl[nt][1] = Bl[(qc + 4) * 136 + C0 + qr];
        }
        #pragma unroll
        for (int mt = 0; mt < 4; mt++)
            #pragma unroll
            for (int nt = 0; nt < 4; nt++) {
                mma16(acc[mt][nt], ah[mt], bh[nt]);
                mma16(acc[mt][nt], al[mt], bh[nt]);
                mma16(acc[mt][nt], ah[mt], bl[nt]);
            }
        __syncthreads();
    }
}

// ================= plain / pooled GEMM =================
template<bool POOL, bool ACC>
__global__ void __launch_bounds__(256, 2) gemm16(
    const uint32_t* __restrict__ Ahg, const uint32_t* __restrict__ Alg,
    const uint32_t* __restrict__ Bhg, const uint32_t* __restrict__ Blg,
    float* __restrict__ Cc, const float* __restrict__ bne, const float* __restrict__ Ein,
    int KP, int lda, int ldb, int ldc, size_t sAz, size_t sBz, size_t sCz)
{
    extern __shared__ __align__(16) uint32_t smbuf[];
    const int z = blockIdx.z;
    const int m0 = blockIdx.y * 128, n0 = blockIdx.x * 128;
    const int tid = threadIdx.x, lane = tid & 31, wrp = tid >> 5;
    const int wm = wrp >> 2, wn = wrp & 3;
    const int qr = lane >> 2, qc = lane & 3;

    float acc[4][4][4];
    #pragma unroll
    for (int i = 0; i < 4; i++)
        #pragma unroll
        for (int j = 0; j < 4; j++)
            #pragma unroll
            for (int q = 0; q < 4; q++) acc[i][j][q] = 0.f;

    GemmPtrs P{Ahg + z * sAz + m0, Alg + z * sAz + m0,
               Bhg + z * sBz + n0, Blg + z * sBz + n0, lda, ldb, KP};
    gemm_mainloop(P, smbuf, tid, wm, wn, qr, qc, acc);

    if (ACC) {
        const float* Eb = Ein + z * sCz;
        #pragma unroll
        for (int mt = 0; mt < 4; mt++)
            #pragma unroll
            for (int nt = 0; nt < 4; nt++) {
                int r = m0 + wm * 64 + mt * 16 + qr;
                int cc = n0 + wn * 32 + nt * 8 + 2 * qc;
                float2 e0 = *(const float2*)(Eb + (size_t)r * NPTS + cc);
                float2 e1 = *(const float2*)(Eb + (size_t)(r + 8) * NPTS + cc);
                acc[mt][nt][0] += e0.x; acc[mt][nt][1] += e0.y;
                acc[mt][nt][2] += e1.x; acc[mt][nt][3] += e1.y;
            }
    }

    if (!POOL) {
        float* Cb = Cc + z * sCz;
        #pragma unroll
        for (int mt = 0; mt < 4; mt++)
            #pragma unroll
            for (int nt = 0; nt < 4; nt++) {
                int r = m0 + wm * 64 + mt * 16 + qr;
                int cc = n0 + wn * 32 + nt * 8 + 2 * qc;
                *(float2*)(Cb + (size_t)r * ldc + cc)       = make_float2(acc[mt][nt][0], acc[mt][nt][1]);
                *(float2*)(Cb + (size_t)(r + 8) * ldc + cc) = make_float2(acc[mt][nt][2], acc[mt][nt][3]);
            }
    } else {
        __shared__ float smax[128][5], ssum[128][5];
        #pragma unroll
        for (int mt = 0; mt < 4; mt++) {
            int rl2 = wm * 64 + mt * 16 + qr;
            int o0 = m0 + rl2, o1 = o0 + 8;
            float s0 = bne[o0] / sqrtf(bne[3072 + o0] + CEPS);
            float b0 = bne[1024 + o0], u0 = bne[2048 + o0];
            float s1 = bne[o1] / sqrtf(bne[3072 + o1] + CEPS);
            float b1 = bne[1024 + o1], u1 = bne[2048 + o1];
            float mx0 = -INFINITY, sm0 = 0.f, mx1 = -INFINITY, sm1 = 0.f;
            #pragma unroll
            for (int nt = 0; nt < 4; nt++) {
                #pragma unroll
                for (int p = 0; p < 2; p++) {
                    float y0 = (acc[mt][nt][p] - u0) * s0 + b0;
                    y0 = (y0 > 0.f) ? y0 : CSLOPE * y0;
                    mx0 = fmaxf(mx0, y0); sm0 += y0;
                    float y1 = (acc[mt][nt][2 + p] - u1) * s1 + b1;
                    y1 = (y1 > 0.f) ? y1 : CSLOPE * y1;
                    mx1 = fmaxf(mx1, y1); sm1 += y1;
                }
            }
            #pragma unroll
            for (int off = 1; off <= 2; off <<= 1) {
                mx0 = fmaxf(mx0, __shfl_xor_sync(0xffffffffu, mx0, off));
                sm0 += __shfl_xor_sync(0xffffffffu, sm0, off);
                mx1 = fmaxf(mx1, __shfl_xor_sync(0xffffffffu, mx1, off));
                sm1 += __shfl_xor_sync(0xffffffffu, sm1, off);
            }
            if (qc == 0) {
                smax[rl2][wn] = mx0; ssum[rl2][wn] = sm0;
                smax[rl2 + 8][wn] = mx1; ssum[rl2 + 8][wn] = sm1;
            }
        }
        __syncthreads();
        if (tid < 128) {
            float mx = -INFINITY, sm = 0.f;
            #pragma unroll
            for (int w = 0; w < 4; w++) { mx = fmaxf(mx, smax[tid][w]); sm += ssum[tid][w]; }
            size_t o = (size_t)z * NPTS + m0 + tid;
            g_pmax[o * 8 + blockIdx.x] = mx;
            g_psum[o * 8 + blockIdx.x] = sm;
        }
    }
}

// ================= merged symmetric-gram + Z + (optional) embed-E1 =================
// blocks [0,36): lower-triangle gram tiles (mirror transpose write);
// blocks [36, 36+8*ZT): Z = cat @ Wt; blocks [36+8*ZT, +ET): E1 = weT x cat.
__global__ void __launch_bounds__(256, 2) gramz_kernel(
    const uint32_t* __restrict__ catH, const uint32_t* __restrict__ catL, int cpo,
    const uint32_t* __restrict__ WtHs, const uint32_t* __restrict__ WtLs,
    float* __restrict__ G, float* __restrict__ Z,
    int KP, int ZT, int ldz,
    const uint32_t* __restrict__ weTH, const uint32_t* __restrict__ weTL,
    float* __restrict__ Ep, int KPE)
{
    extern __shared__ __align__(16) uint32_t smbuf[];
    const int z = blockIdx.z;
    const size_t sCat = (size_t)256 * NPTS;
    const int t = blockIdx.x;
    const int tid = threadIdx.x, lane = tid & 31, wrp = tid >> 5;
    const int wm = wrp >> 2, wn = wrp & 3;
    const int qr = lane >> 2, qc = lane & 3;

    int m0, n0, lda_, ldb_, ldc_, KPl;
    const uint32_t *Ahp, *Alp, *Bhp, *Blp;
    float* Cb;
    bool mirror = false;

    if (t < 36) {
        int ib = 0;
        while ((ib + 1) * (ib + 2) / 2 <= t) ib++;
        int ia = t - ib * (ib + 1) / 2;
        m0 = ia * 128; n0 = ib * 128;
        Ahp = catH + cpo + z * sCat + m0; Alp = catL + cpo + z * sCat + m0;
        Bhp = catH + cpo + z * sCat + n0; Blp = catL + cpo + z * sCat + n0;
        lda_ = NPTS; ldb_ = NPTS; ldc_ = NPTS; KPl = KP;
        Cb = G + (size_t)z * NPTS * NPTS;
        mirror = (ia != ib);
    } else if (t < 36 + 8 * ZT) {
        int t2 = t - 36;
        m0 = (t2 / ZT) * 128; n0 = (t2 % ZT) * 128;
        Ahp = catH + cpo + z * sCat + m0; Alp = catL + cpo + z * sCat + m0;
        Bhp = WtHs + n0; Blp = WtLs + n0;
        lda_ = NPTS; ldb_ = ldz; ldc_ = ldz; KPl = KP;
        Cb = Z + (size_t)z * NPTS * ldz;
    } else {
        int t3 = t - 36 - 8 * ZT;
        m0 = (t3 >> 3) * 128; n0 = (t3 & 7) * 128;
        Ahp = weTH + m0; Alp = weTL + m0;
        Bhp = catH + z * sCat + n0; Blp = catL + z * sCat + n0;
        lda_ = 1024; ldb_ = NPTS; ldc_ = NPTS; KPl = KPE;
        Cb = Ep + (size_t)z * 1024 * NPTS;
    }

    float acc[4][4][4];
    #pragma unroll
    for (int i = 0; i < 4; i++)
        #pragma unroll
        for (int j = 0; j < 4; j++)
            #pragma unroll
            for (int q = 0; q < 4; q++) acc[i][j][q] = 0.f;

    GemmPtrs P{Ahp, Alp, Bhp, Blp, lda_, ldb_, KPl};
    gemm_mainloop(P, smbuf, tid, wm, wn, qr, qc, acc);

    #pragma unroll
    for (int mt = 0; mt < 4; mt++)
        #pragma unroll
        for (int nt = 0; nt < 4; nt++) {
            int r = m0 + wm * 64 + mt * 16 + qr;
            int cc = n0 + wn * 32 + nt * 8 + 2 * qc;
            *(float2*)(Cb + (size_t)r * ldc_ + cc)       = make_float2(acc[mt][nt][0], acc[mt][nt][1]);
            *(float2*)(Cb + (size_t)(r + 8) * ldc_ + cc) = make_float2(acc[mt][nt][2], acc[mt][nt][3]);
        }

    if (mirror) {
        float* S = (float*)smbuf;   // 64 cols x 132 stride = 33.8KB, two passes
        #pragma unroll
        for (int p = 0; p < 2; p++) {
            __syncthreads();
            #pragma unroll
            for (int mt = 0; mt < 4; mt++)
                #pragma unroll
                for (int nt = 0; nt < 4; nt++) {
                    int rl = wm * 64 + mt * 16 + qr;
                    int cl = wn * 32 + nt * 8 + 2 * qc;
                    if ((cl >> 6) == p) {
                        int clo = cl & 63;
                        S[(size_t)clo * 132 + rl]           = acc[mt][nt][0];
                        S[(size_t)(clo + 1) * 132 + rl]     = acc[mt][nt][1];
                        S[(size_t)clo * 132 + rl + 8]       = acc[mt][nt][2];
                        S[(size_t)(clo + 1) * 132 + rl + 8] = acc[mt][nt][3];
                    }
                }
            __syncthreads();
            #pragma unroll
            for (int idx = tid; idx < 2048; idx += 256) {
                int row = idx >> 5, q = idx & 31;
                float4 v = *(const float4*)&S[(size_t)row * 132 + 4 * q];
                *(float4*)(Cb + (size_t)(n0 + p * 64 + row) * NPTS + m0 + 4 * q) = v;
            }
        }
    }
}

// ================= block-1 topk: selection only =================
__global__ void __launch_bounds__(256) topk3_kernel(const float* __restrict__ x) {
    const int tid = threadIdx.x, lane = tid & 31;
    const int gw = blockIdx.x * 8 + (tid >> 5);
    const int b = gw >> 10, n = gw & 1023;
    const float* xb = x + (size_t)b * 3 * NPTS;
    float c0 = xb[n], c1 = xb[NPTS + n], c2 = xb[2 * NPTS + n];
    float d[32];
    #pragma unroll
    for (int j = 0; j < 32; j++) {
        int m = j * 32 + lane;
        float v0 = xb[m], v1 = xb[NPTS + m], v2 = xb[2 * NPTS + m];
        float dot = fmaf(v2, c2, fmaf(v1, c1, fmaf(v0, c0, 0.f)));
        float xxm = fmaf(v2, v2, fmaf(v1, v1, fmaf(v0, v0, 0.f)));
        d[j] = 2.f * dot - xxm;
    }
    int* myidx = g_idx + ((size_t)b * NPTS + n) * KNB;
    float lm = -INFINITY; int lj = 0;
    #pragma unroll
    for (int j = 0; j < 32; j++) if (d[j] > lm) { lm = d[j]; lj = j; }
    for (int k = 0; k < KNB; k++) {
        float bv = lm; int bidx = lj * 32 + lane;
        #pragma unroll
        for (int off = 16; off > 0; off >>= 1) {
            float ov = __shfl_xor_sync(0xffffffffu, bv, off);
            int   oi = __shfl_xor_sync(0xffffffffu, bidx, off);
            if (ov > bv || (ov == bv && oi < bidx)) { bv = ov; bidx = oi; }
        }
        if (lane == (bidx & 31)) {
            int jj = bidx >> 5;
            lm = -INFINITY; lj = 0;
            #pragma unroll
            for (int j = 0; j < 32; j++) {
                if (j == jj) d[j] = -INFINITY;
                if (d[j] > lm) { lm = d[j]; lj = j; }
            }
        }
        if (lane == 0) myidx[k] = bidx;
    }
}

// ================= fused topk + conv-epilogue =================
template<int O, bool WX, bool SEL>
__global__ void __launch_bounds__(256) tkcepi_kernel(const float* __restrict__ bnp, int cout_off) {
    constexpr int NCH = O / 32;
    const int tid = threadIdx.x, lane = tid & 31, wrp = tid >> 5;
    const int b = blockIdx.y;
    const int n = blockIdx.x * 8 + wrp;
    __shared__ float ys[8][O + 2];

    int mysel = 0;
    if (SEL) {
        const float* Grow = g_gram + ((size_t)b * NPTS + n) * NPTS;
        const float* xxb = g_xx + b * NPTS;
        float d[32];
        #pragma unroll
        for (int j = 0; j < 32; j++) {
            int m = j * 32 + lane;
            d[j] = 2.f * Grow[m] - xxb[m];
        }
        float lm = -INFINITY; int lj = 0;
        #pragma unroll
        for (int j = 0; j < 32; j++) if (d[j] > lm) { lm = d[j]; lj = j; }
        for (int k = 0; k < KNB; k++) {
            float bv = lm; int bidx = lj * 32 + lane;
            #pragma unroll
            for (int off = 16; off > 0; off >>= 1) {
                float ov = __shfl_xor_sync(0xffffffffu, bv, off);
                int   oi = __shfl_xor_sync(0xffffffffu, bidx, off);
                if (ov > bv || (ov == bv && oi < bidx)) { bv = ov; bidx = oi; }
            }
            if (lane == (bidx & 31)) {
                int jj = bidx >> 5;
                lm = -INFINITY; lj = 0;
                #pragma unroll
                for (int j = 0; j < 32; j++) {
                    if (j == jj) d[j] = -INFINITY;
                    if (d[j] > lm) { lm = d[j]; lj = j; }
                }
            }
            if (lane == k) mysel = bidx;
        }
    } else {
        if (lane < KNB) mysel = g_idx[((size_t)b * NPTS + n) * KNB + lane];
    }

    const int ld = 2 * O;
    const size_t rowbase = (size_t)b * NPTS;
    float mx[NCH];
    #pragma unroll
    for (int ch = 0; ch < NCH; ch++) mx[ch] = -INFINITY;
    for (int k = 0; k < KNB; k++) {
        int jk = __shfl_sync(0xffffffffu, mysel, k);
        const float* Zr = g_Z + (rowbase + jk) * ld;
        #pragma unroll
        for (int ch = 0; ch < NCH; ch++)
            mx[ch] = fmaxf(mx[ch], Zr[ch * 32 + lane]);
    }
    const float* Zc = g_Z + (rowbase + n) * ld + O;
    float xs = 0.f;
    #pragma unroll
    for (int ch = 0; ch < NCH; ch++) {
        int o = ch * 32 + lane;
        float v = mx[ch] + Zc[o];
        float scale = bnp[o] / sqrtf(bnp[3 * O + o] + CEPS);
        float y = (v - bnp[2 * O + o]) * scale + bnp[O + o];
        y = (y > 0.f) ? y : CSLOPE * y;
        ys[wrp][o] = y;
        if (WX) xs = fmaf(y, y, xs);
    }
    if (WX) {
        #pragma unroll
        for (int off = 16; off > 0; off >>= 1) xs += __shfl_xor_sync(0xffffffffu, xs, off);
        if (lane == 0) g_xx[b * NPTS + n] = xs;
    }
    __syncthreads();

    const int cp0 = cout_off >> 1;
    #pragma unroll
    for (int i = tid; i < 4 * O; i += 256) {
        int nl = i & 7, cp = i >> 3;
        float y0 = ys[nl][2 * cp], y1 = ys[nl][2 * cp + 1];
        size_t w = ((size_t)b * 256 + cp0 + cp) * NPTS + blockIdx.x * 8 + nl;
        g_catH[w] = packh(y0, y1);
        g_catL[w] = packl(y0, y1);
    }
}

// ================= pack =================
__global__ void __launch_bounds__(256) pack_kernel(
    const float* __restrict__ x,
    const float* __restrict__ w0, const float* __restrict__ w1,
    const float* __restrict__ w2, const float* __restrict__ w3,
    const float* __restrict__ we)
{
    const int tid = threadIdx.x;
    {
        __shared__ float s[32][65];
        const int bo = blockIdx.x & 31, bp = blockIdx.x >> 5;
        const int o0 = bo * 32, c0 = bp * 64;
        #pragma unroll
        for (int i = tid; i < 32 * 64; i += 256) {
            int o = i >> 6, c = i & 63;
            s[o][c] = we[(size_t)(o0 + o) * 512 + c0 + c];
        }
        __syncthreads();
        #pragma unroll
        for (int i = tid; i < 32 * 32; i += 256) {
            int p = i >> 5, o = i & 31;
            float v0 = s[o][2 * p], v1 = s[o][2 * p + 1];
            int w = ((c0 >> 1) + p) * 1024 + o0 + o;
            g_weTH[w] = packh(v0, v1);
            g_weTL[w] = packl(v0, v1);
        }
    }
    const int gstride = gridDim.x * 256;
    int gid = blockIdx.x * 256 + tid;
    for (int i = gid; i < BATCH * NPTS; i += gstride) {
        int bb = i >> 10, nn = i & 1023;
        const float* xr = x + (size_t)bb * 3 * NPTS;
        float v0 = xr[nn], v1 = xr[NPTS + nn], v2 = xr[2 * NPTS + nn];
        g_xH[(bb * 2 + 0) * NPTS + nn] = packh(v0, v1);
        g_xL[(bb * 2 + 0) * NPTS + nn] = packl(v0, v1);
        g_xH[(bb * 2 + 1) * NPTS + nn] = packh(v2, 0.f);
        g_xL[(bb * 2 + 1) * NPTS + nn] = packl(v2, 0.f);
    }
    for (int i = gid; i < WTOTU; i += gstride) {
        const float* w; int C, O, loc;
        if (i < WSEG1)      { w = w0; C = 3;   O = 64;  loc = i - WSEG0; }
        else if (i < WSEG2) { w = w1; C = 64;  O = 64;  loc = i - WSEG1; }
        else if (i < WSEG3) { w = w2; C = 64;  O = 128; loc = i - WSEG2; }
        else                { w = w3; C = 128; O = 256; loc = i - WSEG3; }
        int N2 = 2 * O, p = loc / N2, j = loc - p * N2;
        int k0 = 2 * p, k1 = 2 * p + 1;
        float v0, v1;
        if (j < O) {
            v0 = w[(size_t)j * 2 * C + k0];
            v1 = (k1 < C) ? w[(size_t)j * 2 * C + k1] : 0.f;
        } else {
            int o = j - O;
            v0 = w[(size_t)o * 2 * C + C + k0] - w[(size_t)o * 2 * C + k0];
            v1 = (k1 < C) ? (w[(size_t)o * 2 * C + C + k1] - w[(size_t)o * 2 * C + k1]) : 0.f;
        }
        g_WtH[i] = packh(v0, v1);
        g_WtL[i] = packl(v0, v1);
    }
}

// ================= fused MLP head =================
__global__ void __launch_bounds__(1024) head_kernel(
    const float* __restrict__ wf0, const float* __restrict__ bnf0,
    const float* __restrict__ wf1, const float* __restrict__ bnf1,
    const float* __restrict__ wfin, const float* __restrict__ bfin,
    float* __restrict__ out)
{
    const int b = blockIdx.x, tid = threadIdx.x;
    const int w = tid >> 5, lane = tid & 31;
    __shared__ float h0s[2048];
    __shared__ float h1s[512];
    __shared__ float h2s[256];
    {
        int o = tid;
        size_t base = ((size_t)b * NPTS + o) * 8;
        float mx = -INFINITY, sm = 0.f;
        #pragma unroll
        for (int t = 0; t < 8; t++) { mx = fmaxf(mx, g_pmax[base + t]); sm += g_psum[base + t]; }
        h0s[o] = mx;
        h0s[1024 + o] = sm * (1.0f / 1024.0f);
    }
    __syncthreads();
    for (int j = 0; j < 16; j++) {
        int o = w * 16 + j;
        const float* wr = wf0 + (size_t)o * 2048;
        float a = 0.f;
        #pragma unroll 4
        for (int c = lane * 4; c < 2048; c += 128) {
            float4 wv = *(const float4*)(wr + c);
            a = fmaf(wv.x, h0s[c], a);
            a = fmaf(wv.y, h0s[c + 1], a);
            a = fmaf(wv.z, h0s[c + 2], a);
            a = fmaf(wv.w, h0s[c + 3], a);
        }
        #pragma unroll
        for (int off = 16; off > 0; off >>= 1) a += __shfl_xor_sync(0xffffffffu, a, off);
        if (lane == 0) {
            float scale = bnf0[o] / sqrtf(bnf0[1536 + o] + CEPS);
            float y = (a - bnf0[1024 + o]) * scale + bnf0[512 + o];
            h1s[o] = (y > 0.f) ? y : CSLOPE * y;
        }
    }
    __syncthreads();
    for (int j = 0; j < 8; j++) {
        int o = w * 8 + j;
        const float* wr = wf1 + (size_t)o * 512;
        float a = 0.f;
        #pragma unroll
        for (int c = lane * 4; c < 512; c += 128) {
            float4 wv = *(const float4*)(wr + c);
            a = fmaf(wv.x, h1s[c], a);
            a = fmaf(wv.y, h1s[c + 1], a);
            a = fmaf(wv.z, h1s[c + 2], a);
            a = fmaf(wv.w, h1s[c + 3], a);
        }
        #pragma unroll
        for (int off = 16; off > 0; off >>= 1) a += __shfl_xor_sync(0xffffffffu, a, off);
        if (lane == 0) {
            float scale = bnf1[o] / sqrtf(bnf1[768 + o] + CEPS);
            float y = (a - bnf1[512 + o]) * scale + bnf1[256 + o];
            h2s[o] = (y > 0.f) ? y : CSLOPE * y;
        }
    }
    __syncthreads();
    for (int j = 0; j < 2; j++) {
        int o = w * 2 + j;
        const float* wr = wfin + (size_t)o * 256;
        float a = 0.f;
        #pragma unroll
        for (int c = lane * 4; c < 256; c += 128) {
            float4 wv = *(const float4*)(wr + c);
            a = fmaf(wv.x, h2s[c], a);
            a = fmaf(wv.y, h2s[c + 1], a);
            a = fmaf(wv.z, h2s[c + 2], a);
            a = fmaf(wv.w, h2s[c + 3], a);
        }
        #pragma unroll
        for (int off = 16; off > 0; off >>= 1) a += __shfl_xor_sync(0xffffffffu, a, off);
        if (lane == 0) out[b * 64 + o] = bfin[o] + a;
    }
}

// ================= launch =================
#define GSMEM 34816

extern "C" void kernel_launch(void* const* d_in, const int* in_sizes, int n_in,
                              void* d_out, int out_size) {
    const float* x    = (const float*)d_in[0];
    const float* w0   = (const float*)d_in[1];
    const float* w1   = (const float*)d_in[2];
    const float* w2   = (const float*)d_in[3];
    const float* w3   = (const float*)d_in[4];
    const float* bn0  = (const float*)d_in[5];
    const float* bn1  = (const float*)d_in[6];
    const float* bn2  = (const float*)d_in[7];
    const float* bn3  = (const float*)d_in[8];
    const float* we   = (const float*)d_in[9];
    const float* bne  = (const float*)d_in[10];
    const float* wf0  = (const float*)d_in[11];
    const float* bnf0 = (const float*)d_in[12];
    const float* wf1  = (const float*)d_in[13];
    const float* bnf1 = (const float*)d_in[14];
    const float* wfin = (const float*)d_in[15];
    const float* bfin = (const float*)d_in[16];

    static bool s_init = false;
    static cudaStream_t s1;
    static cudaEvent_t evS, evJ0;
    if (!s_init) {
        cudaStreamCreateWithFlags(&s1, cudaStreamNonBlocking);
        cudaEventCreateWithFlags(&evS, cudaEventDisableTiming);
        cudaEventCreateWithFlags(&evJ0, cudaEventDisableTiming);
        cudaFuncSetAttribute(gemm16<false, false>, cudaFuncAttributeMaxDynamicSharedMemorySize, GSMEM);
        cudaFuncSetAttribute(gemm16<true, true>,   cudaFuncAttributeMaxDynamicSharedMemorySize, GSMEM);
        cudaFuncSetAttribute(gramz_kernel,         cudaFuncAttributeMaxDynamicSharedMemorySize, GSMEM);
        s_init = true;
    }

    float *Zp, *gramp, *Ep;
    uint32_t *catHp, *catLp, *WtHp, *WtLp, *weTHp, *weTLp, *xHp, *xLp;
    cudaGetSymbolAddress((void**)&Zp, g_Z);
    cudaGetSymbolAddress((void**)&gramp, g_gram);
    cudaGetSymbolAddress((void**)&Ep, g_E);
    cudaGetSymbolAddress((void**)&catHp, g_catH);
    cudaGetSymbolAddress((void**)&catLp, g_catL);
    cudaGetSymbolAddress((void**)&WtHp, g_WtH);
    cudaGetSymbolAddress((void**)&WtLp, g_WtL);
    cudaGetSymbolAddress((void**)&weTHp, g_weTH);
    cudaGetSymbolAddress((void**)&weTLp, g_weTL);
    cudaGetSymbolAddress((void**)&xHp, g_xH);
    cudaGetSymbolAddress((void**)&xLp, g_xL);

    dim3 gtk(128, BATCH);
    const size_t sCat = (size_t)256 * NPTS;
    cudaStream_t s0 = 0;

    // fork: pack + Z1 on s1; topk3 on main
    cudaEventRecord(evS, s0);
    cudaStreamWaitEvent(s1, evS, 0);
    pack_kernel<<<256, 256, 0, s1>>>(x, w0, w1, w2, w3, we);
    topk3_kernel<<<1024, 256>>>(x);
    gemm16<false, false><<<dim3(1, 8, BATCH), 256, GSMEM, s1>>>(
        xHp, xLp, WtHp + WSEG0, WtLp + WSEG0, Zp, nullptr, nullptr,
        2, NPTS, 128, 128, (size_t)2 * NPTS, 0, (size_t)NPTS * 128);
    cudaEventRecord(evJ0, s1);
    cudaStreamWaitEvent(s0, evJ0, 0);
    tkcepi_kernel<64, true, false><<<gtk, 256>>>(bn0, 0);

    // block 2: sym-gram + Z2
    gramz_kernel<<<dim3(36 + 8, 1, BATCH), 256, GSMEM>>>(
        catHp, catLp, 0, WtHp + WSEG1, WtLp + WSEG1, gramp, Zp, 32, 1, 128,
        weTHp, weTLp, Ep, 128);
    tkcepi_kernel<64, true, true><<<gtk, 256>>>(bn1, 64);

    // block 3: sym-gram + Z3
    gramz_kernel<<<dim3(36 + 16, 1, BATCH), 256, GSMEM>>>(
        catHp, catLp, 32 * NPTS, WtHp + WSEG2, WtLp + WSEG2, gramp, Zp, 32, 2, 256,
        weTHp, weTLp, Ep, 128);
    tkcepi_kernel<128, true, true><<<gtk, 256>>>(bn2, 128);

    // block 4: sym-gram + Z4 + E1 (64 embed tiles, K = first 128 pairs of cat)
    gramz_kernel<<<dim3(36 + 32 + 64, 1, BATCH), 256, GSMEM>>>(
        catHp, catLp, 64 * NPTS, WtHp + WSEG3, WtLp + WSEG3, gramp, Zp, 64, 4, 512,
        weTHp, weTLp, Ep, 128);
    tkcepi_kernel<256, false, true><<<gtk, 256>>>(bn3, 256);

    // E2: second K half + E1 accumulate + fused pool epilogue
    gemm16<true, true><<<dim3(8, 8, BATCH), 256, GSMEM>>>(
        weTHp + 128 * 1024, weTLp + 128 * 1024, catHp + 128 * NPTS, catLp + 128 * NPTS,
        nullptr, bne, Ep,
        128, 1024, NPTS, 0, 0, sCat, (size_t)1024 * NPTS);

    // fused MLP head
    head_kernel<<<BATCH, 1024>>>(wf0, bnf0, wf1, bnf1, wfin, bfin, (float*)d_out);
}

// round 15
// speedup vs baseline: 1.0139x; 1.0139x over previous
#include <cuda_runtime.h>
#include <cuda_fp16.h>
#include <math.h>
#include <stdint.h>

#define NPTS 1024
#define KNB 20
#define BATCH 8
#define CEPS 1e-5f
#define CSLOPE 0.2f

// ---------------- scratch (no allocations allowed) ----------------
__device__ uint32_t g_catH[(size_t)BATCH * 256 * NPTS];
__device__ uint32_t g_catL[(size_t)BATCH * 256 * NPTS];
__device__ float    g_gram[(size_t)BATCH * NPTS * NPTS];
__device__ float    g_E[(size_t)BATCH * 1024 * NPTS];
__device__ float    g_xx[BATCH * NPTS];
__device__ int      g_idx[(size_t)BATCH * NPTS * KNB];
__device__ float    g_Z[(size_t)BATCH * NPTS * 512];
__device__ uint32_t g_WtH[45312], g_WtL[45312];
__device__ uint32_t g_weTH[256 * 1024], g_weTL[256 * 1024];
__device__ uint32_t g_xH[BATCH * 2 * NPTS], g_xL[BATCH * 2 * NPTS];
__device__ float    g_pmax[BATCH * NPTS * 8];
__device__ float    g_psum[BATCH * NPTS * 8];

#define WSEG0 0
#define WSEG1 256
#define WSEG2 4352
#define WSEG3 12544
#define WTOTU 45312

// ================= helpers =================
__device__ __forceinline__ uint32_t packh(float a, float b) {
    __half2 h = __halves2half2(__float2half_rn(a), __float2half_rn(b));
    return *(uint32_t*)&h;
}
__device__ __forceinline__ uint32_t packl(float a, float b) {
    float ra = a - __half2float(__float2half_rn(a));
    float rb = b - __half2float(__float2half_rn(b));
    __half2 h = __halves2half2(__float2half_rn(ra), __float2half_rn(rb));
    return *(uint32_t*)&h;
}
__device__ __forceinline__ void mma16(float* c, const uint32_t* a, const uint32_t* b) {
    asm volatile(
        "mma.sync.aligned.m16n8k16.row.col.f32.f16.f16.f32 "
        "{%0,%1,%2,%3}, {%4,%5,%6,%7}, {%8,%9}, {%0,%1,%2,%3};\n"
        : "+f"(c[0]), "+f"(c[1]), "+f"(c[2]), "+f"(c[3])
        : "r"(a[0]), "r"(a[1]), "r"(a[2]), "r"(a[3]), "r"(b[0]), "r"(b[1]));
}
__device__ __forceinline__ void cpa16(uint32_t s, const void* g, int ok) {
    asm volatile("cp.async.cg.shared.global [%0], [%1], 16, %2;"
                 :: "r"(s), "l"(g), "r"(ok ? 16 : 0));
}
__device__ __forceinline__ void cpa_commit() { asm volatile("cp.async.commit_group;"); }
template<int N> __device__ __forceinline__ void cpa_wait() {
    asm volatile("cp.async.wait_group %0;" :: "n"(N));
}

// ================= shared GEMM core, KC=16 pair-rows/stage (R13-proven) =================
// smem: 2 bufs x 4 arrays x 16x136 u32 = 69632 B. sameAB: skip B staging, alias to A.
struct GemmPtrs {
    const uint32_t *Ah, *Al, *Bh, *Bl;
    int lda, ldb, KP;
    bool sameAB;
};

__device__ __forceinline__ void gemm_mainloop(
    const GemmPtrs& P, uint32_t* smbuf, int tid, int wm, int wn, int qr, int qc,
    float acc[4][4][4])
{
    const int r0 = tid >> 5, c0 = (tid & 31) * 4;
    const int r1 = r0 + 8;
    const uint32_t smbase = (uint32_t)__cvta_generic_to_shared(smbuf);
    const int KT = (P.KP + 15) / 16;
    const bool same = P.sameAB;

    auto issue = [&](int kt, int buf) {
        const int rl = P.KP - kt * 16;
        const size_t ko = (size_t)kt * 16;
        const uint32_t bb = smbase + (uint32_t)buf * (8704u * 4u);
        uint32_t d0 = bb + (uint32_t)(r0 * 136 + c0) * 4u;
        uint32_t d1 = bb + (uint32_t)(r1 * 136 + c0) * 4u;
        cpa16(d0,             P.Ah + (ko + r0) * P.lda + c0, r0 < rl);
        cpa16(d1,             P.Ah + (ko + r1) * P.lda + c0, r1 < rl);
        cpa16(d0 + 2176u * 4, P.Al + (ko + r0) * P.lda + c0, r0 < rl);
        cpa16(d1 + 2176u * 4, P.Al + (ko + r1) * P.lda + c0, r1 < rl);
        if (!same) {
            cpa16(d0 + 4352u * 4, P.Bh + (ko + r0) * P.ldb + c0, r0 < rl);
            cpa16(d1 + 4352u * 4, P.Bh + (ko + r1) * P.ldb + c0, r1 < rl);
            cpa16(d0 + 6528u * 4, P.Bl + (ko + r0) * P.ldb + c0, r0 < rl);
            cpa16(d1 + 6528u * 4, P.Bl + (ko + r1) * P.ldb + c0, r1 < rl);
        }
        cpa_commit();
    };

    issue(0, 0);
    for (int kt = 0; kt < KT; kt++) {
        const int cur = kt & 1;
        if (kt + 1 < KT) { issue(kt + 1, cur ^ 1); cpa_wait<1>(); }
        else             { cpa_wait<0>(); }
        __syncthreads();
        const uint32_t* Ah = smbuf + cur * 8704;
        const uint32_t* Al = Ah + 2176;
        const uint32_t* Bh = same ? Ah : Ah + 4352;
        const uint32_t* Bl = same ? Al : Ah + 6528;
        #pragma unroll
        for (int kk = 0; kk < 2; kk++) {
            const int kb = kk * 8;
            uint32_t ah[4][4], al[4][4], bh[4][2], bl[4][2];
            #pragma unroll
            for (int mt = 0; mt < 4; mt++) {
                int R = wm * 64 + mt * 16;
                ah[mt][0] = Ah[(kb + qc) * 136 + R + qr];
                ah[mt][1] = Ah[(kb + qc) * 136 + R + qr + 8];
                ah[mt][2] = Ah[(kb + qc + 4) * 136 + R + qr];
                ah[mt][3] = Ah[(kb + qc + 4) * 136 + R + qr + 8];
                al[mt][0] = Al[(kb + qc) * 136 + R + qr];
                al[mt][1] = Al[(kb + qc) * 136 + R + qr + 8];
                al[mt][2] = Al[(kb + qc + 4) * 136 + R + qr];
                al[mt][3] = Al[(kb + qc + 4) * 136 + R + qr + 8];
            }
            #pragma unroll
            for (int nt = 0; nt < 4; nt++) {
                int C0 = wn * 32 + nt * 8;
                bh[nt][0] = Bh[(kb + qc) * 136 + C0 + qr];
                bh[nt][1] = Bh[(kb + qc + 4) * 136 + C0 + qr];
                bl[nt][0] = Bl[(kb + qc) * 136 + C0 + qr];
                bl[nt][1] = Bl[(kb + qc + 4) * 136 + C0 + qr];
            }
            #pragma unroll
            for (int mt = 0; mt < 4; mt++)
                #pragma unroll
                for (int nt = 0; nt < 4; nt++) {
                    mma16(acc[mt][nt], ah[mt], bh[nt]);
                    mma16(acc[mt][nt], al[mt], bh[nt]);
                    mma16(acc[mt][nt], ah[mt], bl[nt]);
                }
        }
        __syncthreads();
    }
}

// ================= plain / pooled GEMM =================
template<bool POOL, bool ACC>
__global__ void __launch_bounds__(256) gemm16(
    const uint32_t* __restrict__ Ahg, const uint32_t* __restrict__ Alg,
    const uint32_t* __restrict__ Bhg, const uint32_t* __restrict__ Blg,
    float* __restrict__ Cc, const float* __restrict__ bne, const float* __restrict__ Ein,
    int KP, int lda, int ldb, int ldc, size_t sAz, size_t sBz, size_t sCz)
{
    extern __shared__ __align__(16) uint32_t smbuf[];
    const int z = blockIdx.z;
    const int m0 = blockIdx.y * 128, n0 = blockIdx.x * 128;
    const int tid = threadIdx.x, lane = tid & 31, wrp = tid >> 5;
    const int wm = wrp >> 2, wn = wrp & 3;
    const int qr = lane >> 2, qc = lane & 3;

    float acc[4][4][4];
    #pragma unroll
    for (int i = 0; i < 4; i++)
        #pragma unroll
        for (int j = 0; j < 4; j++)
            #pragma unroll
            for (int q = 0; q < 4; q++) acc[i][j][q] = 0.f;

    GemmPtrs P{Ahg + z * sAz + m0, Alg + z * sAz + m0,
               Bhg + z * sBz + n0, Blg + z * sBz + n0, lda, ldb, KP, false};
    gemm_mainloop(P, smbuf, tid, wm, wn, qr, qc, acc);

    if (ACC) {
        const float* Eb = Ein + z * sCz;
        #pragma unroll
        for (int mt = 0; mt < 4; mt++)
            #pragma unroll
            for (int nt = 0; nt < 4; nt++) {
                int r = m0 + wm * 64 + mt * 16 + qr;
                int cc = n0 + wn * 32 + nt * 8 + 2 * qc;
                float2 e0 = *(const float2*)(Eb + (size_t)r * NPTS + cc);
                float2 e1 = *(const float2*)(Eb + (size_t)(r + 8) * NPTS + cc);
                acc[mt][nt][0] += e0.x; acc[mt][nt][1] += e0.y;
                acc[mt][nt][2] += e1.x; acc[mt][nt][3] += e1.y;
            }
    }

    if (!POOL) {
        float* Cb = Cc + z * sCz;
        #pragma unroll
        for (int mt = 0; mt < 4; mt++)
            #pragma unroll
            for (int nt = 0; nt < 4; nt++) {
                int r = m0 + wm * 64 + mt * 16 + qr;
                int cc = n0 + wn * 32 + nt * 8 + 2 * qc;
                *(float2*)(Cb + (size_t)r * ldc + cc)       = make_float2(acc[mt][nt][0], acc[mt][nt][1]);
                *(float2*)(Cb + (size_t)(r + 8) * ldc + cc) = make_float2(acc[mt][nt][2], acc[mt][nt][3]);
            }
    } else {
        __shared__ float smax[128][5], ssum[128][5];
        #pragma unroll
        for (int mt = 0; mt < 4; mt++) {
            int rl2 = wm * 64 + mt * 16 + qr;
            int o0 = m0 + rl2, o1 = o0 + 8;
            float s0 = bne[o0] / sqrtf(bne[3072 + o0] + CEPS);
            float b0 = bne[1024 + o0], u0 = bne[2048 + o0];
            float s1 = bne[o1] / sqrtf(bne[3072 + o1] + CEPS);
            float b1 = bne[1024 + o1], u1 = bne[2048 + o1];
            float mx0 = -INFINITY, sm0 = 0.f, mx1 = -INFINITY, sm1 = 0.f;
            #pragma unroll
            for (int nt = 0; nt < 4; nt++) {
                #pragma unroll
                for (int p = 0; p < 2; p++) {
                    float y0 = (acc[mt][nt][p] - u0) * s0 + b0;
                    y0 = (y0 > 0.f) ? y0 : CSLOPE * y0;
                    mx0 = fmaxf(mx0, y0); sm0 += y0;
                    float y1 = (acc[mt][nt][2 + p] - u1) * s1 + b1;
                    y1 = (y1 > 0.f) ? y1 : CSLOPE * y1;
                    mx1 = fmaxf(mx1, y1); sm1 += y1;
                }
            }
            #pragma unroll
            for (int off = 1; off <= 2; off <<= 1) {
                mx0 = fmaxf(mx0, __shfl_xor_sync(0xffffffffu, mx0, off));
                sm0 += __shfl_xor_sync(0xffffffffu, sm0, off);
                mx1 = fmaxf(mx1, __shfl_xor_sync(0xffffffffu, mx1, off));
                sm1 += __shfl_xor_sync(0xffffffffu, sm1, off);
            }
            if (qc == 0) {
                smax[rl2][wn] = mx0; ssum[rl2][wn] = sm0;
                smax[rl2 + 8][wn] = mx1; ssum[rl2 + 8][wn] = sm1;
            }
        }
        __syncthreads();
        if (tid < 128) {
            float mx = -INFINITY, sm = 0.f;
            #pragma unroll
            for (int w = 0; w < 4; w++) { mx = fmaxf(mx, smax[tid][w]); sm += ssum[tid][w]; }
            size_t o = (size_t)z * NPTS + m0 + tid;
            g_pmax[o * 8 + blockIdx.x] = mx;
            g_psum[o * 8 + blockIdx.x] = sm;
        }
    }
}

// ================= merged symmetric-gram + Z + (optional) embed-E1 =================
__global__ void __launch_bounds__(256) gramz_kernel(
    const uint32_t* __restrict__ catH, const uint32_t* __restrict__ catL, int cpo,
    const uint32_t* __restrict__ WtHs, const uint32_t* __restrict__ WtLs,
    float* __restrict__ G, float* __restrict__ Z,
    int KP, int ZT, int ldz,
    const uint32_t* __restrict__ weTH, const uint32_t* __restrict__ weTL,
    float* __restrict__ Ep, int KPE)
{
    extern __shared__ __align__(16) uint32_t smbuf[];
    const int z = blockIdx.z;
    const size_t sCat = (size_t)256 * NPTS;
    const int t = blockIdx.x;
    const int tid = threadIdx.x, lane = tid & 31, wrp = tid >> 5;
    const int wm = wrp >> 2, wn = wrp & 3;
    const int qr = lane >> 2, qc = lane & 3;

    int m0, n0, lda_, ldb_, ldc_, KPl;
    const uint32_t *Ahp, *Alp, *Bhp, *Blp;
    float* Cb;
    bool mirror = false, same = false;

    if (t < 36) {
        int ib = 0;
        while ((ib + 1) * (ib + 2) / 2 <= t) ib++;
        int ia = t - ib * (ib + 1) / 2;
        m0 = ia * 128; n0 = ib * 128;
        Ahp = catH + cpo + z * sCat + m0; Alp = catL + cpo + z * sCat + m0;
        Bhp = catH + cpo + z * sCat + n0; Blp = catL + cpo + z * sCat + n0;
        lda_ = NPTS; ldb_ = NPTS; ldc_ = NPTS; KPl = KP;
        Cb = G + (size_t)z * NPTS * NPTS;
        mirror = (ia != ib);
        same = (ia == ib);
    } else if (t < 36 + 8 * ZT) {
        int t2 = t - 36;
        m0 = (t2 / ZT) * 128; n0 = (t2 % ZT) * 128;
        Ahp = catH + cpo + z * sCat + m0; Alp = catL + cpo + z * sCat + m0;
        Bhp = WtHs + n0; Blp = WtLs + n0;
        lda_ = NPTS; ldb_ = ldz; ldc_ = ldz; KPl = KP;
        Cb = Z + (size_t)z * NPTS * ldz;
    } else {
        int t3 = t - 36 - 8 * ZT;
        m0 = (t3 >> 3) * 128; n0 = (t3 & 7) * 128;
        Ahp = weTH + m0; Alp = weTL + m0;
        Bhp = catH + z * sCat + n0; Blp = catL + z * sCat + n0;
        lda_ = 1024; ldb_ = NPTS; ldc_ = NPTS; KPl = KPE;
        Cb = Ep + (size_t)z * 1024 * NPTS;
    }

    float acc[4][4][4];
    #pragma unroll
    for (int i = 0; i < 4; i++)
        #pragma unroll
        for (int j = 0; j < 4; j++)
            #pragma unroll
            for (int q = 0; q < 4; q++) acc[i][j][q] = 0.f;

    GemmPtrs P{Ahp, Alp, Bhp, Blp, lda_, ldb_, KPl, same};
    gemm_mainloop(P, smbuf, tid, wm, wn, qr, qc, acc);

    #pragma unroll
    for (int mt = 0; mt < 4; mt++)
        #pragma unroll
        for (int nt = 0; nt < 4; nt++) {
            int r = m0 + wm * 64 + mt * 16 + qr;
            int cc = n0 + wn * 32 + nt * 8 + 2 * qc;
            *(float2*)(Cb + (size_t)r * ldc_ + cc)       = make_float2(acc[mt][nt][0], acc[mt][nt][1]);
            *(float2*)(Cb + (size_t)(r + 8) * ldc_ + cc) = make_float2(acc[mt][nt][2], acc[mt][nt][3]);
        }

    if (mirror) {
        float* S = (float*)smbuf;   // 128 cols x 132 stride = 67.6KB (fits 69.6KB)
        __syncthreads();
        #pragma unroll
        for (int mt = 0; mt < 4; mt++)
            #pragma unroll
            for (int nt = 0; nt < 4; nt++) {
                int rl = wm * 64 + mt * 16 + qr;
                int cl = wn * 32 + nt * 8 + 2 * qc;
                S[(size_t)cl * 132 + rl]           = acc[mt][nt][0];
                S[(size_t)(cl + 1) * 132 + rl]     = acc[mt][nt][1];
                S[(size_t)cl * 132 + rl + 8]       = acc[mt][nt][2];
                S[(size_t)(cl + 1) * 132 + rl + 8] = acc[mt][nt][3];
            }
        __syncthreads();
        #pragma unroll
        for (int idx = tid; idx < 4096; idx += 256) {
            int row = idx >> 5, q = idx & 31;
            float4 v = *(const float4*)&S[(size_t)row * 132 + 4 * q];
            *(float4*)(Cb + (size_t)(n0 + row) * NPTS + m0 + 4 * q) = v;
        }
    }
}

// ================= block-1 topk: selection only =================
__global__ void __launch_bounds__(256) topk3_kernel(const float* __restrict__ x) {
    const int tid = threadIdx.x, lane = tid & 31;
    const int gw = blockIdx.x * 8 + (tid >> 5);
    const int b = gw >> 10, n = gw & 1023;
    const float* xb = x + (size_t)b * 3 * NPTS;
    float c0 = xb[n], c1 = xb[NPTS + n], c2 = xb[2 * NPTS + n];
    float d[32];
    #pragma unroll
    for (int j = 0; j < 32; j++) {
        int m = j * 32 + lane;
        float v0 = xb[m], v1 = xb[NPTS + m], v2 = xb[2 * NPTS + m];
        float dot = fmaf(v2, c2, fmaf(v1, c1, fmaf(v0, c0, 0.f)));
        float xxm = fmaf(v2, v2, fmaf(v1, v1, fmaf(v0, v0, 0.f)));
        d[j] = 2.f * dot - xxm;
    }
    int* myidx = g_idx + ((size_t)b * NPTS + n) * KNB;
    float lm = -INFINITY; int lj = 0;
    #pragma unroll
    for (int j = 0; j < 32; j++) if (d[j] > lm) { lm = d[j]; lj = j; }
    for (int k = 0; k < KNB; k++) {
        float bv = lm; int bidx = lj * 32 + lane;
        #pragma unroll
        for (int off = 16; off > 0; off >>= 1) {
            float ov = __shfl_xor_sync(0xffffffffu, bv, off);
            int   oi = __shfl_xor_sync(0xffffffffu, bidx, off);
            if (ov > bv || (ov == bv && oi < bidx)) { bv = ov; bidx = oi; }
        }
        if (lane == (bidx & 31)) {
            int jj = bidx >> 5;
            lm = -INFINITY; lj = 0;
            #pragma unroll
            for (int j = 0; j < 32; j++) {
                if (j == jj) d[j] = -INFINITY;
                if (d[j] > lm) { lm = d[j]; lj = j; }
            }
        }
        if (lane == 0) myidx[k] = bidx;
    }
}

// ================= fused topk + conv-epilogue =================
template<int O, bool WX, bool SEL>
__global__ void __launch_bounds__(256) tkcepi_kernel(const float* __restrict__ bnp, int cout_off) {
    constexpr int NCH = O / 32;
    const int tid = threadIdx.x, lane = tid & 31, wrp = tid >> 5;
    const int b = blockIdx.y;
    const int n = blockIdx.x * 8 + wrp;
    __shared__ float ys[8][O + 2];
    __shared__ int jids[8][KNB];

    int mysel = 0;
    if (SEL) {
        const float* Grow = g_gram + ((size_t)b * NPTS + n) * NPTS;
        const float* xxb = g_xx + b * NPTS;
        float d[32];
        #pragma unroll
        for (int j = 0; j < 32; j++) {
            int m = j * 32 + lane;
            d[j] = 2.f * Grow[m] - xxb[m];
        }
        float lm = -INFINITY; int lj = 0;
        #pragma unroll
        for (int j = 0; j < 32; j++) if (d[j] > lm) { lm = d[j]; lj = j; }
        for (int k = 0; k < KNB; k++) {
            float bv = lm; int bidx = lj * 32 + lane;
            #pragma unroll
            for (int off = 16; off > 0; off >>= 1) {
                float ov = __shfl_xor_sync(0xffffffffu, bv, off);
                int   oi = __shfl_xor_sync(0xffffffffu, bidx, off);
                if (ov > bv || (ov == bv && oi < bidx)) { bv = ov; bidx = oi; }
            }
            if (lane == (bidx & 31)) {
                int jj = bidx >> 5;
                lm = -INFINITY; lj = 0;
                #pragma unroll
                for (int j = 0; j < 32; j++) {
                    if (j == jj) d[j] = -INFINITY;
                    if (d[j] > lm) { lm = d[j]; lj = j; }
                }
            }
            if (lane == k) mysel = bidx;
        }
    } else {
        if (lane < KNB) mysel = g_idx[((size_t)b * NPTS + n) * KNB + lane];
    }
    if (lane < KNB) jids[wrp][lane] = mysel;
    __syncwarp();

    const int ld = 2 * O;
    const size_t rowbase = (size_t)b * NPTS;
    float mx[NCH];
    #pragma unroll
    for (int ch = 0; ch < NCH; ch++) mx[ch] = -INFINITY;
    #pragma unroll 4
    for (int k = 0; k < KNB; k++) {
        const float* Zr = g_Z + (rowbase + jids[wrp][k]) * ld;
        #pragma unroll
        for (int ch = 0; ch < NCH; ch++)
            mx[ch] = fmaxf(mx[ch], Zr[ch * 32 + lane]);
    }
    const float* Zc = g_Z + (rowbase + n) * ld + O;
    float xs = 0.f;
    #pragma unroll
    for (int ch = 0; ch < NCH; ch++) {
        int o = ch * 32 + lane;
        float v = mx[ch] + Zc[o];
        float scale = bnp[o] / sqrtf(bnp[3 * O + o] + CEPS);
        float y = (v - bnp[2 * O + o]) * scale + bnp[O + o];
        y = (y > 0.f) ? y : CSLOPE * y;
        ys[wrp][o] = y;
        if (WX) xs = fmaf(y, y, xs);
    }
    if (WX) {
        #pragma unroll
        for (int off = 16; off > 0; off >>= 1) xs += __shfl_xor_sync(0xffffffffu, xs, off);
        if (lane == 0) g_xx[b * NPTS + n] = xs;
    }
    __syncthreads();

    const int cp0 = cout_off >> 1;
    #pragma unroll
    for (int i = tid; i < 4 * O; i += 256) {
        int nl = i & 7, cp = i >> 3;
        float y0 = ys[nl][2 * cp], y1 = ys[nl][2 * cp + 1];
        size_t w = ((size_t)b * 256 + cp0 + cp) * NPTS + blockIdx.x * 8 + nl;
        g_catH[w] = packh(y0, y1);
        g_catL[w] = packl(y0, y1);
    }
}

// ================= pack =================
__global__ void __launch_bounds__(256) pack_kernel(
    const float* __restrict__ x,
    const float* __restrict__ w0, const float* __restrict__ w1,
    const float* __restrict__ w2, const float* __restrict__ w3,
    const float* __restrict__ we)
{
    const int tid = threadIdx.x;
    {
        __shared__ float s[32][65];
        const int bo = blockIdx.x & 31, bp = blockIdx.x >> 5;
        const int o0 = bo * 32, c0 = bp * 64;
        #pragma unroll
        for (int i = tid; i < 32 * 64; i += 256) {
            int o = i >> 6, c = i & 63;
            s[o][c] = we[(size_t)(o0 + o) * 512 + c0 + c];
        }
        __syncthreads();
        #pragma unroll
        for (int i = tid; i < 32 * 32; i += 256) {
            int p = i >> 5, o = i & 31;
            float v0 = s[o][2 * p], v1 = s[o][2 * p + 1];
            int w = ((c0 >> 1) + p) * 1024 + o0 + o;
            g_weTH[w] = packh(v0, v1);
            g_weTL[w] = packl(v0, v1);
        }
    }
    const int gstride = gridDim.x * 256;
    int gid = blockIdx.x * 256 + tid;
    for (int i = gid; i < BATCH * NPTS; i += gstride) {
        int bb = i >> 10, nn = i & 1023;
        const float* xr = x + (size_t)bb * 3 * NPTS;
        float v0 = xr[nn], v1 = xr[NPTS + nn], v2 = xr[2 * NPTS + nn];
        g_xH[(bb * 2 + 0) * NPTS + nn] = packh(v0, v1);
        g_xL[(bb * 2 + 0) * NPTS + nn] = packl(v0, v1);
        g_xH[(bb * 2 + 1) * NPTS + nn] = packh(v2, 0.f);
        g_xL[(bb * 2 + 1) * NPTS + nn] = packl(v2, 0.f);
    }
    for (int i = gid; i < WTOTU; i += gstride) {
        const float* w; int C, O, loc;
        if (i < WSEG1)      { w = w0; C = 3;   O = 64;  loc = i - WSEG0; }
        else if (i < WSEG2) { w = w1; C = 64;  O = 64;  loc = i - WSEG1; }
        else if (i < WSEG3) { w = w2; C = 64;  O = 128; loc = i - WSEG2; }
        else                { w = w3; C = 128; O = 256; loc = i - WSEG3; }
        int N2 = 2 * O, p = loc / N2, j = loc - p * N2;
        int k0 = 2 * p, k1 = 2 * p + 1;
        float v0, v1;
        if (j < O) {
            v0 = w[(size_t)j * 2 * C + k0];
            v1 = (k1 < C) ? w[(size_t)j * 2 * C + k1] : 0.f;
        } else {
            int o = j - O;
            v0 = w[(size_t)o * 2 * C + C + k0] - w[(size_t)o * 2 * C + k0];
            v1 = (k1 < C) ? (w[(size_t)o * 2 * C + C + k1] - w[(size_t)o * 2 * C + k1]) : 0.f;
        }
        g_WtH[i] = packh(v0, v1);
        g_WtL[i] = packl(v0, v1);
    }
}

// ================= fused MLP head =================
__global__ void __launch_bounds__(1024) head_kernel(
    const float* __restrict__ wf0, const float* __restrict__ bnf0,
    const float* __restrict__ wf1, const float* __restrict__ bnf1,
    const float* __restrict__ wfin, const float* __restrict__ bfin,
    float* __restrict__ out)
{
    const int b = blockIdx.x, tid = threadIdx.x;
    const int w = tid >> 5, lane = tid & 31;
    __shared__ float h0s[2048];
    __shared__ float h1s[512];
    __shared__ float h2s[256];
    {
        int o = tid;
        size_t base = ((size_t)b * NPTS + o) * 8;
        float mx = -INFINITY, sm = 0.f;
        #pragma unroll
        for (int t = 0; t < 8; t++) { mx = fmaxf(mx, g_pmax[base + t]); sm += g_psum[base + t]; }
        h0s[o] = mx;
        h0s[1024 + o] = sm * (1.0f / 1024.0f);
    }
    __syncthreads();
    for (int j = 0; j < 16; j++) {
        int o = w * 16 + j;
        const float* wr = wf0 + (size_t)o * 2048;
        float a = 0.f;
        #pragma unroll 4
        for (int c = lane * 4; c < 2048; c += 128) {
            float4 wv = *(const float4*)(wr + c);
            a = fmaf(wv.x, h0s[c], a);
            a = fmaf(wv.y, h0s[c + 1], a);
            a = fmaf(wv.z, h0s[c + 2], a);
            a = fmaf(wv.w, h0s[c + 3], a);
        }
        #pragma unroll
        for (int off = 16; off > 0; off >>= 1) a += __shfl_xor_sync(0xffffffffu, a, off);
        if (lane == 0) {
            float scale = bnf0[o] / sqrtf(bnf0[1536 + o] + CEPS);
            float y = (a - bnf0[1024 + o]) * scale + bnf0[512 + o];
            h1s[o] = (y > 0.f) ? y : CSLOPE * y;
        }
    }
    __syncthreads();
    for (int j = 0; j < 8; j++) {
        int o = w * 8 + j;
        const float* wr = wf1 + (size_t)o * 512;
        float a = 0.f;
        #pragma unroll
        for (int c = lane * 4; c < 512; c += 128) {
            float4 wv = *(const float4*)(wr + c);
            a = fmaf(wv.x, h1s[c], a);
            a = fmaf(wv.y, h1s[c + 1], a);
            a = fmaf(wv.z, h1s[c + 2], a);
            a = fmaf(wv.w, h1s[c + 3], a);
        }
        #pragma unroll
        for (int off = 16; off > 0; off >>= 1) a += __shfl_xor_sync(0xffffffffu, a, off);
        if (lane == 0) {
            float scale = bnf1[o] / sqrtf(bnf1[768 + o] + CEPS);
            float y = (a - bnf1[512 + o]) * scale + bnf1[256 + o];
            h2s[o] = (y > 0.f) ? y : CSLOPE * y;
        }
    }
    __syncthreads();
    for (int j = 0; j < 2; j++) {
        int o = w * 2 + j;
        const float* wr = wfin + (size_t)o * 256;
        float a = 0.f;
        #pragma unroll
        for (int c = lane * 4; c < 256; c += 128) {
            float4 wv = *(const float4*)(wr + c);
            a = fmaf(wv.x, h2s[c], a);
            a = fmaf(wv.y, h2s[c + 1], a);
            a = fmaf(wv.z, h2s[c + 2], a);
            a = fmaf(wv.w, h2s[c + 3], a);
        }
        #pragma unroll
        for (int off = 16; off > 0; off >>= 1) a += __shfl_xor_sync(0xffffffffu, a, off);
        if (lane == 0) out[b * 64 + o] = bfin[o] + a;
    }
}

// ================= launch =================
#define GSMEM 69632

extern "C" void kernel_launch(void* const* d_in, const int* in_sizes, int n_in,
                              void* d_out, int out_size) {
    const float* x    = (const float*)d_in[0];
    const float* w0   = (const float*)d_in[1];
    const float* w1   = (const float*)d_in[2];
    const float* w2   = (const float*)d_in[3];
    const float* w3   = (const float*)d_in[4];
    const float* bn0  = (const float*)d_in[5];
    const float* bn1  = (const float*)d_in[6];
    const float* bn2  = (const float*)d_in[7];
    const float* bn3  = (const float*)d_in[8];
    const float* we   = (const float*)d_in[9];
    const float* bne  = (const float*)d_in[10];
    const float* wf0  = (const float*)d_in[11];
    const float* bnf0 = (const float*)d_in[12];
    const float* wf1  = (const float*)d_in[13];
    const float* bnf1 = (const float*)d_in[14];
    const float* wfin = (const float*)d_in[15];
    const float* bfin = (const float*)d_in[16];

    static bool s_init = false;
    static cudaStream_t s1;
    static cudaEvent_t evS, evJ0;
    if (!s_init) {
        cudaStreamCreateWithFlags(&s1, cudaStreamNonBlocking);
        cudaEventCreateWithFlags(&evS, cudaEventDisableTiming);
        cudaEventCreateWithFlags(&evJ0, cudaEventDisableTiming);
        cudaFuncSetAttribute(gemm16<false, false>, cudaFuncAttributeMaxDynamicSharedMemorySize, GSMEM);
        cudaFuncSetAttribute(gemm16<true, true>,   cudaFuncAttributeMaxDynamicSharedMemorySize, GSMEM);
        cudaFuncSetAttribute(gramz_kernel,         cudaFuncAttributeMaxDynamicSharedMemorySize, GSMEM);
        s_init = true;
    }

    float *Zp, *gramp, *Ep;
    uint32_t *catHp, *catLp, *WtHp, *WtLp, *weTHp, *weTLp, *xHp, *xLp;
    cudaGetSymbolAddress((void**)&Zp, g_Z);
    cudaGetSymbolAddress((void**)&gramp, g_gram);
    cudaGetSymbolAddress((void**)&Ep, g_E);
    cudaGetSymbolAddress((void**)&catHp, g_catH);
    cudaGetSymbolAddress((void**)&catLp, g_catL);
    cudaGetSymbolAddress((void**)&WtHp, g_WtH);
    cudaGetSymbolAddress((void**)&WtLp, g_WtL);
    cudaGetSymbolAddress((void**)&weTHp, g_weTH);
    cudaGetSymbolAddress((void**)&weTLp, g_weTL);
    cudaGetSymbolAddress((void**)&xHp, g_xH);
    cudaGetSymbolAddress((void**)&xLp, g_xL);

    dim3 gtk(128, BATCH);
    const size_t sCat = (size_t)256 * NPTS;
    cudaStream_t s0 = 0;

    // fork: pack + Z1 on s1; topk3 on main
    cudaEventRecord(evS, s0);
    cudaStreamWaitEvent(s1, evS, 0);
    pack_kernel<<<256, 256, 0, s1>>>(x, w0, w1, w2, w3, we);
    topk3_kernel<<<1024, 256>>>(x);
    gemm16<false, false><<<dim3(1, 8, BATCH), 256, GSMEM, s1>>>(
        xHp, xLp, WtHp + WSEG0, WtLp + WSEG0, Zp, nullptr, nullptr,
        2, NPTS, 128, 128, (size_t)2 * NPTS, 0, (size_t)NPTS * 128);
    cudaEventRecord(evJ0, s1);
    cudaStreamWaitEvent(s0, evJ0, 0);
    tkcepi_kernel<64, true, false><<<gtk, 256>>>(bn0, 0);

    // block 2: sym-gram + Z2
    gramz_kernel<<<dim3(36 + 8, 1, BATCH), 256, GSMEM>>>(
        catHp, catLp, 0, WtHp + WSEG1, WtLp + WSEG1, gramp, Zp, 32, 1, 128,
        weTHp, weTLp, Ep, 128);
    tkcepi_kernel<64, true, true><<<gtk, 256>>>(bn1, 64);

    // block 3: sym-gram + Z3
    gramz_kernel<<<dim3(36 + 16, 1, BATCH), 256, GSMEM>>>(
        catHp, catLp, 32 * NPTS, WtHp + WSEG2, WtLp + WSEG2, gramp, Zp, 32, 2, 256,
        weTHp, weTLp, Ep, 128);
    tkcepi_kernel<128, true, true><<<gtk, 256>>>(bn2, 128);

    // block 4: sym-gram + Z4 + E1 (64 embed tiles over first 128 k-pairs of cat)
    gramz_kernel<<<dim3(36 + 32 + 64, 1, BATCH), 256, GSMEM>>>(
        catHp, catLp, 64 * NPTS, WtHp + WSEG3, WtLp + WSEG3, gramp, Zp, 64, 4, 512,
        weTHp, weTLp, Ep, 128);
    tkcepi_kernel<256, false, true><<<gtk, 256>>>(bn3, 256);

    // E2: second K half + E1 accumulate + fused pool epilogue
    gemm16<true, true><<<dim3(8, 8, BATCH), 256, GSMEM>>>(
        weTHp + 128 * 1024, weTLp + 128 * 1024, catHp + 128 * NPTS, catLp + 128 * NPTS,
        nullptr, bne, Ep,
        128, 1024, NPTS, 0, 0, sCat, (size_t)1024 * NPTS);

    // fused MLP head
    head_kernel<<<BATCH, 1024>>>(wf0, bnf0, wf1, bnf1, wfin, bfin, (float*)d_out);
}

// round 16
// speedup vs baseline: 1.0203x; 1.0063x over previous
#include <cuda_runtime.h>
#include <cuda_fp16.h>
#include <math.h>
#include <stdint.h>

#define NPTS 1024
#define KNB 20
#define BATCH 8
#define CEPS 1e-5f
#define CSLOPE 0.2f

// ---------------- scratch (no allocations allowed) ----------------
__device__ uint32_t g_catH[(size_t)BATCH * 256 * NPTS];
__device__ uint32_t g_catL[(size_t)BATCH * 256 * NPTS];
__device__ float    g_gram[(size_t)BATCH * NPTS * NPTS];
__device__ float    g_E[(size_t)BATCH * 1024 * NPTS];
__device__ float    g_xx[BATCH * NPTS];
__device__ int      g_idx[(size_t)BATCH * NPTS * KNB];
__device__ float    g_Z[(size_t)BATCH * NPTS * 512];
__device__ float    g_h1[BATCH * 512];
__device__ uint32_t g_WtH[45312], g_WtL[45312];
__device__ uint32_t g_weTH[256 * 1024], g_weTL[256 * 1024];
__device__ uint32_t g_xH[BATCH * 2 * NPTS], g_xL[BATCH * 2 * NPTS];
__device__ float    g_pmax[BATCH * NPTS * 8];
__device__ float    g_psum[BATCH * NPTS * 8];

#define WSEG0 0
#define WSEG1 256
#define WSEG2 4352
#define WSEG3 12544
#define WTOTU 45312

// ================= helpers =================
__device__ __forceinline__ uint32_t packh(float a, float b) {
    __half2 h = __halves2half2(__float2half_rn(a), __float2half_rn(b));
    return *(uint32_t*)&h;
}
__device__ __forceinline__ uint32_t packl(float a, float b) {
    float ra = a - __half2float(__float2half_rn(a));
    float rb = b - __half2float(__float2half_rn(b));
    __half2 h = __halves2half2(__float2half_rn(ra), __float2half_rn(rb));
    return *(uint32_t*)&h;
}
__device__ __forceinline__ void mma16(float* c, const uint32_t* a, const uint32_t* b) {
    asm volatile(
        "mma.sync.aligned.m16n8k16.row.col.f32.f16.f16.f32 "
        "{%0,%1,%2,%3}, {%4,%5,%6,%7}, {%8,%9}, {%0,%1,%2,%3};\n"
        : "+f"(c[0]), "+f"(c[1]), "+f"(c[2]), "+f"(c[3])
        : "r"(a[0]), "r"(a[1]), "r"(a[2]), "r"(a[3]), "r"(b[0]), "r"(b[1]));
}
__device__ __forceinline__ void cpa16(uint32_t s, const void* g, int ok) {
    asm volatile("cp.async.cg.shared.global [%0], [%1], 16, %2;"
                 :: "r"(s), "l"(g), "r"(ok ? 16 : 0));
}
__device__ __forceinline__ void cpa_commit() { asm volatile("cp.async.commit_group;"); }
template<int N> __device__ __forceinline__ void cpa_wait() {
    asm volatile("cp.async.wait_group %0;" :: "n"(N));
}

// ================= shared GEMM core, KC=16 pair-rows/stage =================
struct GemmPtrs {
    const uint32_t *Ah, *Al, *Bh, *Bl;
    int lda, ldb, KP;
    bool sameAB;
};

__device__ __forceinline__ void gemm_mainloop(
    const GemmPtrs& P, uint32_t* smbuf, int tid, int wm, int wn, int qr, int qc,
    float acc[4][4][4])
{
    const int r0 = tid >> 5, c0 = (tid & 31) * 4;
    const int r1 = r0 + 8;
    const uint32_t smbase = (uint32_t)__cvta_generic_to_shared(smbuf);
    const int KT = (P.KP + 15) / 16;
    const bool same = P.sameAB;

    auto issue = [&](int kt, int buf) {
        const int rl = P.KP - kt * 16;
        const size_t ko = (size_t)kt * 16;
        const uint32_t bb = smbase + (uint32_t)buf * (8704u * 4u);
        uint32_t d0 = bb + (uint32_t)(r0 * 136 + c0) * 4u;
        uint32_t d1 = bb + (uint32_t)(r1 * 136 + c0) * 4u;
        cpa16(d0,             P.Ah + (ko + r0) * P.lda + c0, r0 < rl);
        cpa16(d1,             P.Ah + (ko + r1) * P.lda + c0, r1 < rl);
        cpa16(d0 + 2176u * 4, P.Al + (ko + r0) * P.lda + c0, r0 < rl);
        cpa16(d1 + 2176u * 4, P.Al + (ko + r1) * P.lda + c0, r1 < rl);
        if (!same) {
            cpa16(d0 + 4352u * 4, P.Bh + (ko + r0) * P.ldb + c0, r0 < rl);
            cpa16(d1 + 4352u * 4, P.Bh + (ko + r1) * P.ldb + c0, r1 < rl);
            cpa16(d0 + 6528u * 4, P.Bl + (ko + r0) * P.ldb + c0, r0 < rl);
            cpa16(d1 + 6528u * 4, P.Bl + (ko + r1) * P.ldb + c0, r1 < rl);
        }
        cpa_commit();
    };

    issue(0, 0);
    for (int kt = 0; kt < KT; kt++) {
        const int cur = kt & 1;
        if (kt + 1 < KT) { issue(kt + 1, cur ^ 1); cpa_wait<1>(); }
        else             { cpa_wait<0>(); }
        __syncthreads();
        const uint32_t* Ah = smbuf + cur * 8704;
        const uint32_t* Al = Ah + 2176;
        const uint32_t* Bh = same ? Ah : Ah + 4352;
        const uint32_t* Bl = same ? Al : Ah + 6528;
        #pragma unroll
        for (int kk = 0; kk < 2; kk++) {
            const int kb = kk * 8;
            uint32_t ah[4][4], al[4][4], bh[4][2], bl[4][2];
            #pragma unroll
            for (int mt = 0; mt < 4; mt++) {
                int R = wm * 64 + mt * 16;
                ah[mt][0] = Ah[(kb + qc) * 136 + R + qr];
                ah[mt][1] = Ah[(kb + qc) * 136 + R + qr + 8];
                ah[mt][2] = Ah[(kb + qc + 4) * 136 + R + qr];
                ah[mt][3] = Ah[(kb + qc + 4) * 136 + R + qr + 8];
                al[mt][0] = Al[(kb + qc) * 136 + R + qr];
                al[mt][1] = Al[(kb + qc) * 136 + R + qr + 8];
                al[mt][2] = Al[(kb + qc + 4) * 136 + R + qr];
                al[mt][3] = Al[(kb + qc + 4) * 136 + R + qr + 8];
            }
            #pragma unroll
            for (int nt = 0; nt < 4; nt++) {
                int C0 = wn * 32 + nt * 8;
                bh[nt][0] = Bh[(kb + qc) * 136 + C0 + qr];
                bh[nt][1] = Bh[(kb + qc + 4) * 136 + C0 + qr];
                bl[nt][0] = Bl[(kb + qc) * 136 + C0 + qr];
                bl[nt][1] = Bl[(kb + qc + 4) * 136 + C0 + qr];
            }
            #pragma unroll
            for (int mt = 0; mt < 4; mt++)
                #pragma unroll
                for (int nt = 0; nt < 4; nt++) {
                    mma16(acc[mt][nt], ah[mt], bh[nt]);
                    mma16(acc[mt][nt], al[mt], bh[nt]);
                    mma16(acc[mt][nt], ah[mt], bl[nt]);
                }
        }
        __syncthreads();
    }
}

// ================= plain / pooled GEMM =================
template<bool POOL, bool ACC>
__global__ void __launch_bounds__(256) gemm16(
    const uint32_t* __restrict__ Ahg, const uint32_t* __restrict__ Alg,
    const uint32_t* __restrict__ Bhg, const uint32_t* __restrict__ Blg,
    float* __restrict__ Cc, const float* __restrict__ bne, const float* __restrict__ Ein,
    int KP, int lda, int ldb, int ldc, size_t sAz, size_t sBz, size_t sCz)
{
    extern __shared__ __align__(16) uint32_t smbuf[];
    const int z = blockIdx.z;
    const int m0 = blockIdx.y * 128, n0 = blockIdx.x * 128;
    const int tid = threadIdx.x, lane = tid & 31, wrp = tid >> 5;
    const int wm = wrp >> 2, wn = wrp & 3;
    const int qr = lane >> 2, qc = lane & 3;

    float acc[4][4][4];
    #pragma unroll
    for (int i = 0; i < 4; i++)
        #pragma unroll
        for (int j = 0; j < 4; j++)
            #pragma unroll
            for (int q = 0; q < 4; q++) acc[i][j][q] = 0.f;

    GemmPtrs P{Ahg + z * sAz + m0, Alg + z * sAz + m0,
               Bhg + z * sBz + n0, Blg + z * sBz + n0, lda, ldb, KP, false};
    gemm_mainloop(P, smbuf, tid, wm, wn, qr, qc, acc);

    if (ACC) {
        const float* Eb = Ein + z * sCz;
        #pragma unroll
        for (int mt = 0; mt < 4; mt++)
            #pragma unroll
            for (int nt = 0; nt < 4; nt++) {
                int r = m0 + wm * 64 + mt * 16 + qr;
                int cc = n0 + wn * 32 + nt * 8 + 2 * qc;
                float2 e0 = *(const float2*)(Eb + (size_t)r * NPTS + cc);
                float2 e1 = *(const float2*)(Eb + (size_t)(r + 8) * NPTS + cc);
                acc[mt][nt][0] += e0.x; acc[mt][nt][1] += e0.y;
                acc[mt][nt][2] += e1.x; acc[mt][nt][3] += e1.y;
            }
    }

    if (!POOL) {
        float* Cb = Cc + z * sCz;
        #pragma unroll
        for (int mt = 0; mt < 4; mt++)
            #pragma unroll
            for (int nt = 0; nt < 4; nt++) {
                int r = m0 + wm * 64 + mt * 16 + qr;
                int cc = n0 + wn * 32 + nt * 8 + 2 * qc;
                *(float2*)(Cb + (size_t)r * ldc + cc)       = make_float2(acc[mt][nt][0], acc[mt][nt][1]);
                *(float2*)(Cb + (size_t)(r + 8) * ldc + cc) = make_float2(acc[mt][nt][2], acc[mt][nt][3]);
            }
    } else {
        __shared__ float smax[128][5], ssum[128][5];
        #pragma unroll
        for (int mt = 0; mt < 4; mt++) {
            int rl2 = wm * 64 + mt * 16 + qr;
            int o0 = m0 + rl2, o1 = o0 + 8;
            float s0 = bne[o0] / sqrtf(bne[3072 + o0] + CEPS);
            float b0 = bne[1024 + o0], u0 = bne[2048 + o0];
            float s1 = bne[o1] / sqrtf(bne[3072 + o1] + CEPS);
            float b1 = bne[1024 + o1], u1 = bne[2048 + o1];
            float mx0 = -INFINITY, sm0 = 0.f, mx1 = -INFINITY, sm1 = 0.f;
            #pragma unroll
            for (int nt = 0; nt < 4; nt++) {
                #pragma unroll
                for (int p = 0; p < 2; p++) {
                    float y0 = (acc[mt][nt][p] - u0) * s0 + b0;
                    y0 = (y0 > 0.f) ? y0 : CSLOPE * y0;
                    mx0 = fmaxf(mx0, y0); sm0 += y0;
                    float y1 = (acc[mt][nt][2 + p] - u1) * s1 + b1;
                    y1 = (y1 > 0.f) ? y1 : CSLOPE * y1;
                    mx1 = fmaxf(mx1, y1); sm1 += y1;
                }
            }
            #pragma unroll
            for (int off = 1; off <= 2; off <<= 1) {
                mx0 = fmaxf(mx0, __shfl_xor_sync(0xffffffffu, mx0, off));
                sm0 += __shfl_xor_sync(0xffffffffu, sm0, off);
                mx1 = fmaxf(mx1, __shfl_xor_sync(0xffffffffu, mx1, off));
                sm1 += __shfl_xor_sync(0xffffffffu, sm1, off);
            }
            if (qc == 0) {
                smax[rl2][wn] = mx0; ssum[rl2][wn] = sm0;
                smax[rl2 + 8][wn] = mx1; ssum[rl2 + 8][wn] = sm1;
            }
        }
        __syncthreads();
        if (tid < 128) {
            float mx = -INFINITY, sm = 0.f;
            #pragma unroll
            for (int w = 0; w < 4; w++) { mx = fmaxf(mx, smax[tid][w]); sm += ssum[tid][w]; }
            size_t o = (size_t)z * NPTS + m0 + tid;
            g_pmax[o * 8 + blockIdx.x] = mx;
            g_psum[o * 8 + blockIdx.x] = sm;
        }
    }
}

// ================= merged gram + Z + embed-E1, long-tiles-first schedule =================
// blocks [0,ET): E1 tiles (KP=KPE, longest — scheduled first, LPT);
// blocks [ET, ET+36): lower-triangle gram tiles (mirror write);
// blocks [ET+36, ET+36+8*ZT): Z tiles.
__global__ void __launch_bounds__(256) gramz_kernel(
    const uint32_t* __restrict__ catH, const uint32_t* __restrict__ catL, int cpo,
    const uint32_t* __restrict__ WtHs, const uint32_t* __restrict__ WtLs,
    float* __restrict__ G, float* __restrict__ Z,
    int KP, int ZT, int ldz,
    const uint32_t* __restrict__ weTH, const uint32_t* __restrict__ weTL,
    float* __restrict__ Ep, int KPE, int ET)
{
    extern __shared__ __align__(16) uint32_t smbuf[];
    const int z = blockIdx.z;
    const size_t sCat = (size_t)256 * NPTS;
    const int t = blockIdx.x;
    const int tid = threadIdx.x, lane = tid & 31, wrp = tid >> 5;
    const int wm = wrp >> 2, wn = wrp & 3;
    const int qr = lane >> 2, qc = lane & 3;

    int m0, n0, lda_, ldb_, ldc_, KPl;
    const uint32_t *Ahp, *Alp, *Bhp, *Blp;
    float* Cb;
    bool mirror = false, same = false;

    if (t < ET) {
        m0 = (t >> 3) * 128; n0 = (t & 7) * 128;
        Ahp = weTH + m0; Alp = weTL + m0;
        Bhp = catH + z * sCat + n0; Blp = catL + z * sCat + n0;
        lda_ = 1024; ldb_ = NPTS; ldc_ = NPTS; KPl = KPE;
        Cb = Ep + (size_t)z * 1024 * NPTS;
    } else if (t < ET + 36) {
        int tg = t - ET;
        int ib = 0;
        while ((ib + 1) * (ib + 2) / 2 <= tg) ib++;
        int ia = tg - ib * (ib + 1) / 2;
        m0 = ia * 128; n0 = ib * 128;
        Ahp = catH + cpo + z * sCat + m0; Alp = catL + cpo + z * sCat + m0;
        Bhp = catH + cpo + z * sCat + n0; Blp = catL + cpo + z * sCat + n0;
        lda_ = NPTS; ldb_ = NPTS; ldc_ = NPTS; KPl = KP;
        Cb = G + (size_t)z * NPTS * NPTS;
        mirror = (ia != ib);
        same = (ia == ib);
    } else {
        int t2 = t - ET - 36;
        m0 = (t2 / ZT) * 128; n0 = (t2 % ZT) * 128;
        Ahp = catH + cpo + z * sCat + m0; Alp = catL + cpo + z * sCat + m0;
        Bhp = WtHs + n0; Blp = WtLs + n0;
        lda_ = NPTS; ldb_ = ldz; ldc_ = ldz; KPl = KP;
        Cb = Z + (size_t)z * NPTS * ldz;
    }

    float acc[4][4][4];
    #pragma unroll
    for (int i = 0; i < 4; i++)
        #pragma unroll
        for (int j = 0; j < 4; j++)
            #pragma unroll
            for (int q = 0; q < 4; q++) acc[i][j][q] = 0.f;

    GemmPtrs P{Ahp, Alp, Bhp, Blp, lda_, ldb_, KPl, same};
    gemm_mainloop(P, smbuf, tid, wm, wn, qr, qc, acc);

    #pragma unroll
    for (int mt = 0; mt < 4; mt++)
        #pragma unroll
        for (int nt = 0; nt < 4; nt++) {
            int r = m0 + wm * 64 + mt * 16 + qr;
            int cc = n0 + wn * 32 + nt * 8 + 2 * qc;
            *(float2*)(Cb + (size_t)r * ldc_ + cc)       = make_float2(acc[mt][nt][0], acc[mt][nt][1]);
            *(float2*)(Cb + (size_t)(r + 8) * ldc_ + cc) = make_float2(acc[mt][nt][2], acc[mt][nt][3]);
        }

    if (mirror) {
        float* S = (float*)smbuf;
        __syncthreads();
        #pragma unroll
        for (int mt = 0; mt < 4; mt++)
            #pragma unroll
            for (int nt = 0; nt < 4; nt++) {
                int rl = wm * 64 + mt * 16 + qr;
                int cl = wn * 32 + nt * 8 + 2 * qc;
                S[(size_t)cl * 132 + rl]           = acc[mt][nt][0];
                S[(size_t)(cl + 1) * 132 + rl]     = acc[mt][nt][1];
                S[(size_t)cl * 132 + rl + 8]       = acc[mt][nt][2];
                S[(size_t)(cl + 1) * 132 + rl + 8] = acc[mt][nt][3];
            }
        __syncthreads();
        #pragma unroll
        for (int idx = tid; idx < 4096; idx += 256) {
            int row = idx >> 5, q = idx & 31;
            float4 v = *(const float4*)&S[(size_t)row * 132 + 4 * q];
            *(float4*)(Cb + (size_t)(n0 + row) * NPTS + m0 + 4 * q) = v;
        }
    }
}

// ================= block-1 topk: selection only =================
__global__ void __launch_bounds__(256) topk3_kernel(const float* __restrict__ x) {
    const int tid = threadIdx.x, lane = tid & 31;
    const int gw = blockIdx.x * 8 + (tid >> 5);
    const int b = gw >> 10, n = gw & 1023;
    const float* xb = x + (size_t)b * 3 * NPTS;
    float c0 = xb[n], c1 = xb[NPTS + n], c2 = xb[2 * NPTS + n];
    float d[32];
    #pragma unroll
    for (int j = 0; j < 32; j++) {
        int m = j * 32 + lane;
        float v0 = xb[m], v1 = xb[NPTS + m], v2 = xb[2 * NPTS + m];
        float dot = fmaf(v2, c2, fmaf(v1, c1, fmaf(v0, c0, 0.f)));
        float xxm = fmaf(v2, v2, fmaf(v1, v1, fmaf(v0, v0, 0.f)));
        d[j] = 2.f * dot - xxm;
    }
    int* myidx = g_idx + ((size_t)b * NPTS + n) * KNB;
    float lm = -INFINITY; int lj = 0;
    #pragma unroll
    for (int j = 0; j < 32; j++) if (d[j] > lm) { lm = d[j]; lj = j; }
    for (int k = 0; k < KNB; k++) {
        float bv = lm; int bidx = lj * 32 + lane;
        #pragma unroll
        for (int off = 16; off > 0; off >>= 1) {
            float ov = __shfl_xor_sync(0xffffffffu, bv, off);
            int   oi = __shfl_xor_sync(0xffffffffu, bidx, off);
            if (ov > bv || (ov == bv && oi < bidx)) { bv = ov; bidx = oi; }
        }
        if (lane == (bidx & 31)) {
            int jj = bidx >> 5;
            lm = -INFINITY; lj = 0;
            #pragma unroll
            for (int j = 0; j < 32; j++) {
                if (j == jj) d[j] = -INFINITY;
                if (d[j] > lm) { lm = d[j]; lj = j; }
            }
        }
        if (lane == 0) myidx[k] = bidx;
    }
}

// ================= fused topk + conv-epilogue =================
template<int O, bool WX, bool SEL>
__global__ void __launch_bounds__(256) tkcepi_kernel(const float* __restrict__ bnp, int cout_off) {
    constexpr int NCH = O / 32;
    const int tid = threadIdx.x, lane = tid & 31, wrp = tid >> 5;
    const int b = blockIdx.y;
    const int n = blockIdx.x * 8 + wrp;
    __shared__ float ys[8][O + 2];
    __shared__ int jids[8][KNB];

    int mysel = 0;
    if (SEL) {
        const float* Grow = g_gram + ((size_t)b * NPTS + n) * NPTS;
        const float* xxb = g_xx + b * NPTS;
        float d[32];
        #pragma unroll
        for (int j = 0; j < 32; j++) {
            int m = j * 32 + lane;
            d[j] = 2.f * Grow[m] - xxb[m];
        }
        float lm = -INFINITY; int lj = 0;
        #pragma unroll
        for (int j = 0; j < 32; j++) if (d[j] > lm) { lm = d[j]; lj = j; }
        for (int k = 0; k < KNB; k++) {
            float bv = lm; int bidx = lj * 32 + lane;
            #pragma unroll
            for (int off = 16; off > 0; off >>= 1) {
                float ov = __shfl_xor_sync(0xffffffffu, bv, off);
                int   oi = __shfl_xor_sync(0xffffffffu, bidx, off);
                if (ov > bv || (ov == bv && oi < bidx)) { bv = ov; bidx = oi; }
            }
            if (lane == (bidx & 31)) {
                int jj = bidx >> 5;
                lm = -INFINITY; lj = 0;
                #pragma unroll
                for (int j = 0; j < 32; j++) {
                    if (j == jj) d[j] = -INFINITY;
                    if (d[j] > lm) { lm = d[j]; lj = j; }
                }
            }
            if (lane == k) mysel = bidx;
        }
    } else {
        if (lane < KNB) mysel = g_idx[((size_t)b * NPTS + n) * KNB + lane];
    }
    if (lane < KNB) jids[wrp][lane] = mysel;
    __syncwarp();

    const int ld = 2 * O;
    const size_t rowbase = (size_t)b * NPTS;
    float mx[NCH];
    #pragma unroll
    for (int ch = 0; ch < NCH; ch++) mx[ch] = -INFINITY;
    #pragma unroll 4
    for (int k = 0; k < KNB; k++) {
        const float* Zr = g_Z + (rowbase + jids[wrp][k]) * ld;
        #pragma unroll
        for (int ch = 0; ch < NCH; ch++)
            mx[ch] = fmaxf(mx[ch], Zr[ch * 32 + lane]);
    }
    const float* Zc = g_Z + (rowbase + n) * ld + O;
    float xs = 0.f;
    #pragma unroll
    for (int ch = 0; ch < NCH; ch++) {
        int o = ch * 32 + lane;
        float v = mx[ch] + Zc[o];
        float scale = bnp[o] / sqrtf(bnp[3 * O + o] + CEPS);
        float y = (v - bnp[2 * O + o]) * scale + bnp[O + o];
        y = (y > 0.f) ? y : CSLOPE * y;
        ys[wrp][o] = y;
        if (WX) xs = fmaf(y, y, xs);
    }
    if (WX) {
        #pragma unroll
        for (int off = 16; off > 0; off >>= 1) xs += __shfl_xor_sync(0xffffffffu, xs, off);
        if (lane == 0) g_xx[b * NPTS + n] = xs;
    }
    __syncthreads();

    const int cp0 = cout_off >> 1;
    #pragma unroll
    for (int i = tid; i < 4 * O; i += 256) {
        int nl = i & 7, cp = i >> 3;
        float y0 = ys[nl][2 * cp], y1 = ys[nl][2 * cp + 1];
        size_t w = ((size_t)b * 256 + cp0 + cp) * NPTS + blockIdx.x * 8 + nl;
        g_catH[w] = packh(y0, y1);
        g_catL[w] = packl(y0, y1);
    }
}

// ================= pack =================
__global__ void __launch_bounds__(256) pack_kernel(
    const float* __restrict__ x,
    const float* __restrict__ w0, const float* __restrict__ w1,
    const float* __restrict__ w2, const float* __restrict__ w3,
    const float* __restrict__ we)
{
    const int tid = threadIdx.x;
    {
        __shared__ float s[32][65];
        const int bo = blockIdx.x & 31, bp = blockIdx.x >> 5;
        const int o0 = bo * 32, c0 = bp * 64;
        #pragma unroll
        for (int i = tid; i < 32 * 64; i += 256) {
            int o = i >> 6, c = i & 63;
            s[o][c] = we[(size_t)(o0 + o) * 512 + c0 + c];
        }
        __syncthreads();
        #pragma unroll
        for (int i = tid; i < 32 * 32; i += 256) {
            int p = i >> 5, o = i & 31;
            float v0 = s[o][2 * p], v1 = s[o][2 * p + 1];
            int w = ((c0 >> 1) + p) * 1024 + o0 + o;
            g_weTH[w] = packh(v0, v1);
            g_weTL[w] = packl(v0, v1);
        }
    }
    const int gstride = gridDim.x * 256;
    int gid = blockIdx.x * 256 + tid;
    for (int i = gid; i < BATCH * NPTS; i += gstride) {
        int bb = i >> 10, nn = i & 1023;
        const float* xr = x + (size_t)bb * 3 * NPTS;
        float v0 = xr[nn], v1 = xr[NPTS + nn], v2 = xr[2 * NPTS + nn];
        g_xH[(bb * 2 + 0) * NPTS + nn] = packh(v0, v1);
        g_xL[(bb * 2 + 0) * NPTS + nn] = packl(v0, v1);
        g_xH[(bb * 2 + 1) * NPTS + nn] = packh(v2, 0.f);
        g_xL[(bb * 2 + 1) * NPTS + nn] = packl(v2, 0.f);
    }
    for (int i = gid; i < WTOTU; i += gstride) {
        const float* w; int C, O, loc;
        if (i < WSEG1)      { w = w0; C = 3;   O = 64;  loc = i - WSEG0; }
        else if (i < WSEG2) { w = w1; C = 64;  O = 64;  loc = i - WSEG1; }
        else if (i < WSEG3) { w = w2; C = 64;  O = 128; loc = i - WSEG2; }
        else                { w = w3; C = 128; O = 256; loc = i - WSEG3; }
        int N2 = 2 * O, p = loc / N2, j = loc - p * N2;
        int k0 = 2 * p, k1 = 2 * p + 1;
        float v0, v1;
        if (j < O) {
            v0 = w[(size_t)j * 2 * C + k0];
            v1 = (k1 < C) ? w[(size_t)j * 2 * C + k1] : 0.f;
        } else {
            int o = j - O;
            v0 = w[(size_t)o * 2 * C + C + k0] - w[(size_t)o * 2 * C + k0];
            v1 = (k1 < C) ? (w[(size_t)o * 2 * C + C + k1] - w[(size_t)o * 2 * C + k1]) : 0.f;
        }
        g_WtH[i] = packh(v0, v1);
        g_WtL[i] = packl(v0, v1);
    }
}

// ================= MLP head, stage 1: pools + layer-1 quarter per block =================
__global__ void __launch_bounds__(512) head1_kernel(
    const float* __restrict__ wf0, const float* __restrict__ bnf0)
{
    const int b = blockIdx.x, q = blockIdx.y;   // q: which 128-output quarter
    const int tid = threadIdx.x;
    const int w = tid >> 5, lane = tid & 31;    // 16 warps
    __shared__ float h0s[2048];

    for (int o = tid; o < 1024; o += 512) {
        size_t base = ((size_t)b * NPTS + o) * 8;
        float mx = -INFINITY, sm = 0.f;
        #pragma unroll
        for (int t = 0; t < 8; t++) { mx = fmaxf(mx, g_pmax[base + t]); sm += g_psum[base + t]; }
        h0s[o] = mx;
        h0s[1024 + o] = sm * (1.0f / 1024.0f);
    }
    __syncthreads();

    for (int j = 0; j < 8; j++) {
        int o = q * 128 + w * 8 + j;
        const float* wr = wf0 + (size_t)o * 2048;
        float a = 0.f;
        #pragma unroll 4
        for (int c = lane * 4; c < 2048; c += 128) {
            float4 wv = *(const float4*)(wr + c);
            a = fmaf(wv.x, h0s[c], a);
            a = fmaf(wv.y, h0s[c + 1], a);
            a = fmaf(wv.z, h0s[c + 2], a);
            a = fmaf(wv.w, h0s[c + 3], a);
        }
        #pragma unroll
        for (int off = 16; off > 0; off >>= 1) a += __shfl_xor_sync(0xffffffffu, a, off);
        if (lane == 0) {
            float scale = bnf0[o] / sqrtf(bnf0[1536 + o] + CEPS);
            float y = (a - bnf0[1024 + o]) * scale + bnf0[512 + o];
            g_h1[b * 512 + o] = (y > 0.f) ? y : CSLOPE * y;
        }
    }
}

// ================= MLP head, stage 2: layers 2-3 =================
__global__ void __launch_bounds__(512) head2_kernel(
    const float* __restrict__ wf1, const float* __restrict__ bnf1,
    const float* __restrict__ wfin, const float* __restrict__ bfin,
    float* __restrict__ out)
{
    const int b = blockIdx.x, tid = threadIdx.x;
    const int w = tid >> 5, lane = tid & 31;   // 16 warps
    __shared__ float h1s[512];
    __shared__ float h2s[256];

    h1s[tid] = g_h1[b * 512 + tid];
    __syncthreads();

    for (int j = 0; j < 16; j++) {
        int o = w * 16 + j;
        const float* wr = wf1 + (size_t)o * 512;
        float a = 0.f;
        #pragma unroll
        for (int c = lane * 4; c < 512; c += 128) {
            float4 wv = *(const float4*)(wr + c);
            a = fmaf(wv.x, h1s[c], a);
            a = fmaf(wv.y, h1s[c + 1], a);
            a = fmaf(wv.z, h1s[c + 2], a);
            a = fmaf(wv.w, h1s[c + 3], a);
        }
        #pragma unroll
        for (int off = 16; off > 0; off >>= 1) a += __shfl_xor_sync(0xffffffffu, a, off);
        if (lane == 0) {
            float scale = bnf1[o] / sqrtf(bnf1[768 + o] + CEPS);
            float y = (a - bnf1[512 + o]) * scale + bnf1[256 + o];
            h2s[o] = (y > 0.f) ? y : CSLOPE * y;
        }
    }
    __syncthreads();

    for (int j = 0; j < 4; j++) {
        int o = w * 4 + j;
        const float* wr = wfin + (size_t)o * 256;
        float a = 0.f;
        #pragma unroll
        for (int c = lane * 4; c < 256; c += 128) {
            float4 wv = *(const float4*)(wr + c);
            a = fmaf(wv.x, h2s[c], a);
            a = fmaf(wv.y, h2s[c + 1], a);
            a = fmaf(wv.z, h2s[c + 2], a);
            a = fmaf(wv.w, h2s[c + 3], a);
        }
        #pragma unroll
        for (int off = 16; off > 0; off >>= 1) a += __shfl_xor_sync(0xffffffffu, a, off);
        if (lane == 0) out[b * 64 + o] = bfin[o] + a;
    }
}

// ================= launch =================
#define GSMEM 69632

extern "C" void kernel_launch(void* const* d_in, const int* in_sizes, int n_in,
                              void* d_out, int out_size) {
    const float* x    = (const float*)d_in[0];
    const float* w0   = (const float*)d_in[1];
    const float* w1   = (const float*)d_in[2];
    const float* w2   = (const float*)d_in[3];
    const float* w3   = (const float*)d_in[4];
    const float* bn0  = (const float*)d_in[5];
    const float* bn1  = (const float*)d_in[6];
    const float* bn2  = (const float*)d_in[7];
    const float* bn3  = (const float*)d_in[8];
    const float* we   = (const float*)d_in[9];
    const float* bne  = (const float*)d_in[10];
    const float* wf0  = (const float*)d_in[11];
    const float* bnf0 = (const float*)d_in[12];
    const float* wf1  = (const float*)d_in[13];
    const float* bnf1 = (const float*)d_in[14];
    const float* wfin = (const float*)d_in[15];
    const float* bfin = (const float*)d_in[16];

    static bool s_init = false;
    static cudaStream_t s1;
    static cudaEvent_t evS, evJ0;
    if (!s_init) {
        cudaStreamCreateWithFlags(&s1, cudaStreamNonBlocking);
        cudaEventCreateWithFlags(&evS, cudaEventDisableTiming);
        cudaEventCreateWithFlags(&evJ0, cudaEventDisableTiming);
        cudaFuncSetAttribute(gemm16<false, false>, cudaFuncAttributeMaxDynamicSharedMemorySize, GSMEM);
        cudaFuncSetAttribute(gemm16<true, true>,   cudaFuncAttributeMaxDynamicSharedMemorySize, GSMEM);
        cudaFuncSetAttribute(gramz_kernel,         cudaFuncAttributeMaxDynamicSharedMemorySize, GSMEM);
        s_init = true;
    }

    float *Zp, *gramp, *Ep;
    uint32_t *catHp, *catLp, *WtHp, *WtLp, *weTHp, *weTLp, *xHp, *xLp;
    cudaGetSymbolAddress((void**)&Zp, g_Z);
    cudaGetSymbolAddress((void**)&gramp, g_gram);
    cudaGetSymbolAddress((void**)&Ep, g_E);
    cudaGetSymbolAddress((void**)&catHp, g_catH);
    cudaGetSymbolAddress((void**)&catLp, g_catL);
    cudaGetSymbolAddress((void**)&WtHp, g_WtH);
    cudaGetSymbolAddress((void**)&WtLp, g_WtL);
    cudaGetSymbolAddress((void**)&weTHp, g_weTH);
    cudaGetSymbolAddress((void**)&weTLp, g_weTL);
    cudaGetSymbolAddress((void**)&xHp, g_xH);
    cudaGetSymbolAddress((void**)&xLp, g_xL);

    dim3 gtk(128, BATCH);
    const size_t sCat = (size_t)256 * NPTS;
    cudaStream_t s0 = 0;

    // fork: pack + Z1 on s1; topk3 on main
    cudaEventRecord(evS, s0);
    cudaStreamWaitEvent(s1, evS, 0);
    pack_kernel<<<256, 256, 0, s1>>>(x, w0, w1, w2, w3, we);
    topk3_kernel<<<1024, 256>>>(x);
    gemm16<false, false><<<dim3(1, 8, BATCH), 256, GSMEM, s1>>>(
        xHp, xLp, WtHp + WSEG0, WtLp + WSEG0, Zp, nullptr, nullptr,
        2, NPTS, 128, 128, (size_t)2 * NPTS, 0, (size_t)NPTS * 128);
    cudaEventRecord(evJ0, s1);
    cudaStreamWaitEvent(s0, evJ0, 0);
    tkcepi_kernel<64, true, false><<<gtk, 256>>>(bn0, 0);

    // block 2: gram + Z2
    gramz_kernel<<<dim3(36 + 8, 1, BATCH), 256, GSMEM>>>(
        catHp, catLp, 0, WtHp + WSEG1, WtLp + WSEG1, gramp, Zp, 32, 1, 128,
        weTHp, weTLp, Ep, 128, 0);
    tkcepi_kernel<64, true, true><<<gtk, 256>>>(bn1, 64);

    // block 3: gram + Z3
    gramz_kernel<<<dim3(36 + 16, 1, BATCH), 256, GSMEM>>>(
        catHp, catLp, 32 * NPTS, WtHp + WSEG2, WtLp + WSEG2, gramp, Zp, 32, 2, 256,
        weTHp, weTLp, Ep, 128, 0);
    tkcepi_kernel<128, true, true><<<gtk, 256>>>(bn2, 128);

    // block 4: E1 tiles FIRST (KP=128, longest), then gram + Z4 (KP=64)
    gramz_kernel<<<dim3(64 + 36 + 32, 1, BATCH), 256, GSMEM>>>(
        catHp, catLp, 64 * NPTS, WtHp + WSEG3, WtLp + WSEG3, gramp, Zp, 64, 4, 512,
        weTHp, weTLp, Ep, 128, 64);
    tkcepi_kernel<256, false, true><<<gtk, 256>>>(bn3, 256);

    // E2: second K half + E1 accumulate + fused pool epilogue
    gemm16<true, true><<<dim3(8, 8, BATCH), 256, GSMEM>>>(
        weTHp + 128 * 1024, weTLp + 128 * 1024, catHp + 128 * NPTS, catLp + 128 * NPTS,
        nullptr, bne, Ep,
        128, 1024, NPTS, 0, 0, sCat, (size_t)1024 * NPTS);

    // split MLP head: layer-1 parallelized 4x, then layers 2-3
    head1_kernel<<<dim3(BATCH, 4), 512>>>(wf0, bnf0);
    head2_kernel<<<BATCH, 512>>>(wf1, bnf1, wfin, bfin, (float*)d_out);
}